// round 3
// baseline (speedup 1.0000x reference)
#include <cuda_runtime.h>
#include <cuda_bf16.h>

// Problem constants
#define PB   256      // batch
#define PE   512      // embed dim
#define PC   8192     // classes
#define PK   10       // centers per class
#define PN   (PC*PK)  // 81920 rows of fc
#define LMD        10.0f
#define INV_GAMMA  10.0f
#define TAU        0.2f
#define MARGIN     0.01f

// Scratch (static device globals; no allocation allowed)
__device__ float g_w[(size_t)PN * PE];     // normalized centers, fp32
__device__ float g_h[(size_t)PB * PC];     // soft-pooled class similarity
__device__ float g_regpart[PC];            // per-class regularizer partial
__device__ float g_rowloss[PB];            // per-batch-row CE loss

// strict-upper-triangle pair index tables for K=10 (45 pairs)
__constant__ int c_pk[45] = {0,0,0,0,0,0,0,0,0, 1,1,1,1,1,1,1,1, 2,2,2,2,2,2,2,
                             3,3,3,3,3,3, 4,4,4,4,4, 5,5,5,5, 6,6,6, 7,7, 8};
__constant__ int c_pj[45] = {1,2,3,4,5,6,7,8,9, 2,3,4,5,6,7,8,9, 3,4,5,6,7,8,9,
                             4,5,6,7,8,9, 5,6,7,8,9, 6,7,8,9, 7,8,9, 8,9, 9};

// ---------------------------------------------------------------------------
// Kernel 1: per-class row L2-normalization + gram regularizer partial.
// One block per class: 10 rows x 512 in smem, 10 warps (warp r owns row r).
// ---------------------------------------------------------------------------
__global__ void k_norm_reg(const float* __restrict__ fc)
{
    __shared__ float sw[10][PE];
    __shared__ float wpart[10];

    const int c    = blockIdx.x;
    const int warp = threadIdx.x >> 5;
    const int lane = threadIdx.x & 31;

    if (warp < 10) {
        const float* row = fc + ((size_t)c * PK + warp) * PE;
        float ss = 0.f;
#pragma unroll
        for (int q = 0; q < 4; q++) {
            float4 t = reinterpret_cast<const float4*>(row)[lane + 32 * q];
            reinterpret_cast<float4*>(&sw[warp][0])[lane + 32 * q] = t;
            ss += t.x * t.x + t.y * t.y + t.z * t.z + t.w * t.w;
        }
#pragma unroll
        for (int o = 16; o; o >>= 1) ss += __shfl_xor_sync(0xffffffffu, ss, o);
        const float inv = 1.0f / fmaxf(sqrtf(ss), 1e-12f);
        float* gw = g_w + ((size_t)c * PK + warp) * PE;
#pragma unroll
        for (int q = 0; q < 4; q++) {
            float4 t = reinterpret_cast<float4*>(&sw[warp][0])[lane + 32 * q];
            t.x *= inv; t.y *= inv; t.z *= inv; t.w *= inv;
            reinterpret_cast<float4*>(&sw[warp][0])[lane + 32 * q] = t;
            reinterpret_cast<float4*>(gw)[lane + 32 * q] = t;
        }
    }
    __syncthreads();

    // 45 gram pairs split across 10 warps; each pair = warp-cooperative dot(512)
    float acc = 0.f;
    for (int p = warp; p < 45; p += 10) {
        const int a = c_pk[p], b = c_pj[p];
        float d = 0.f;
#pragma unroll
        for (int q = 0; q < 4; q++) {
            float4 va = reinterpret_cast<const float4*>(&sw[a][0])[lane + 32 * q];
            float4 vb = reinterpret_cast<const float4*>(&sw[b][0])[lane + 32 * q];
            d += va.x * vb.x + va.y * vb.y + va.z * vb.z + va.w * vb.w;
        }
#pragma unroll
        for (int o = 16; o; o >>= 1) d += __shfl_xor_sync(0xffffffffu, d, o);
        float s = 1.0f - d;
        s = (s <= 0.f) ? 1e-10f : s;
        acc += sqrtf(2.0f * s);
    }
    if (lane == 0) wpart[warp] = acc;
    __syncthreads();
    if (threadIdx.x == 0) {
        float t = 0.f;
#pragma unroll
        for (int i = 0; i < 10; i++) t += wpart[i];
        g_regpart[c] = t;
    }
}

// ---------------------------------------------------------------------------
// Kernel 2: GEMM x = emb @ w.T with fused softmax-pool over K=10.
// Block tile: 64 (batch) x 160 (rows = 16 classes), BK=16.
// Thread tile: 4 (m) x 10 (n) -> each thread owns one full class => softpool
// is a register-only epilogue. Writes g_h[b][c].
// ---------------------------------------------------------------------------
#define BM 64
#define BN 160
#define BK 16
__global__ __launch_bounds__(256, 2) void k_gemm(const float* __restrict__ emb)
{
    __shared__ float As[BK][BM];   // 4 KB
    __shared__ float Bs[BK][BN];   // 10 KB

    const int tid = threadIdx.x;
    const int tx  = tid & 15;      // class within block
    const int ty  = tid >> 4;      // m group
    const int m0  = blockIdx.y * BM;
    const int n0  = blockIdx.x * BN;

    float acc[4][10];
#pragma unroll
    for (int i = 0; i < 4; i++)
#pragma unroll
        for (int j = 0; j < 10; j++) acc[i][j] = 0.f;

    for (int k0 = 0; k0 < PE; k0 += BK) {
        // stage A: 64 rows x 16 cols = 256 float4, one per thread (transposed)
        {
            const int row = tid >> 2, quad = tid & 3;
            float4 t = reinterpret_cast<const float4*>(emb + (m0 + row) * PE + k0)[quad];
            As[quad * 4 + 0][row] = t.x;
            As[quad * 4 + 1][row] = t.y;
            As[quad * 4 + 2][row] = t.z;
            As[quad * 4 + 3][row] = t.w;
        }
        // stage B: 160 rows x 16 cols = 640 float4
        for (int idx = tid; idx < 640; idx += 256) {
            const int row = idx >> 2, quad = idx & 3;
            float4 t = reinterpret_cast<const float4*>(g_w + (size_t)(n0 + row) * PE + k0)[quad];
            Bs[quad * 4 + 0][row] = t.x;
            Bs[quad * 4 + 1][row] = t.y;
            Bs[quad * 4 + 2][row] = t.z;
            Bs[quad * 4 + 3][row] = t.w;
        }
        __syncthreads();
#pragma unroll
        for (int kk = 0; kk < BK; kk++) {
            float4 av = *reinterpret_cast<const float4*>(&As[kk][ty * 4]);
            const float a0 = av.x, a1 = av.y, a2 = av.z, a3 = av.w;
            float b[10];
            const float2* bp = reinterpret_cast<const float2*>(&Bs[kk][tx * 10]);
#pragma unroll
            for (int q = 0; q < 5; q++) {
                float2 t = bp[q];
                b[2 * q] = t.x; b[2 * q + 1] = t.y;
            }
#pragma unroll
            for (int j = 0; j < 10; j++) {
                acc[0][j] = fmaf(a0, b[j], acc[0][j]);
                acc[1][j] = fmaf(a1, b[j], acc[1][j]);
                acc[2][j] = fmaf(a2, b[j], acc[2][j]);
                acc[3][j] = fmaf(a3, b[j], acc[3][j]);
            }
        }
        __syncthreads();
    }

    // softpool epilogue: h = sum_k softmax(10*x)_k * x_k  (per thread: 4 rows x 1 class)
    const int c = blockIdx.x * 16 + tx;
#pragma unroll
    for (int mi = 0; mi < 4; mi++) {
        float mx = acc[mi][0];
#pragma unroll
        for (int j = 1; j < 10; j++) mx = fmaxf(mx, acc[mi][j]);
        float s = 0.f, hs = 0.f;
#pragma unroll
        for (int j = 0; j < 10; j++) {
            const float x = acc[mi][j];
            const float e = __expf(INV_GAMMA * (x - mx));
            s  += e;
            hs += e * x;
        }
        g_h[(size_t)(m0 + ty * 4 + mi) * PC + c] = hs / s;
    }
}

// ---------------------------------------------------------------------------
// Kernel 3: per-batch-row cross entropy with margin at label.
// labels are int32 (JAX x64 disabled -> int64 request silently yields int32).
// ---------------------------------------------------------------------------
__global__ void k_ce(const int* __restrict__ labels)
{
    __shared__ float sred[256];
    const int b   = blockIdx.x;
    const int tid = threadIdx.x;
    const float* row = g_h + (size_t)b * PC;
    const int lab = labels[b];

    float mx = -3.0e38f;
    for (int i = tid; i < PC; i += 256) {
        float v = LMD * row[i] - ((i == lab) ? (LMD * MARGIN) : 0.f);
        mx = fmaxf(mx, v);
    }
    sred[tid] = mx; __syncthreads();
    for (int o = 128; o; o >>= 1) {
        if (tid < o) sred[tid] = fmaxf(sred[tid], sred[tid + o]);
        __syncthreads();
    }
    mx = sred[0];
    __syncthreads();

    float s = 0.f;
    for (int i = tid; i < PC; i += 256) {
        float v = LMD * row[i] - ((i == lab) ? (LMD * MARGIN) : 0.f);
        s += __expf(v - mx);
    }
    sred[tid] = s; __syncthreads();
    for (int o = 128; o; o >>= 1) {
        if (tid < o) sred[tid] += sred[tid + o];
        __syncthreads();
    }
    if (tid == 0) {
        const float v = LMD * row[lab] - LMD * MARGIN;
        g_rowloss[b] = -(v - mx - logf(sred[0]));
    }
}

// ---------------------------------------------------------------------------
// Kernel 4: deterministic final reduce: mean CE + TAU * reg
// ---------------------------------------------------------------------------
__global__ void k_final(float* __restrict__ out)
{
    __shared__ float sred[256];
    const int tid = threadIdx.x;

    sred[tid] = g_rowloss[tid];
    __syncthreads();
    for (int o = 128; o; o >>= 1) {
        if (tid < o) sred[tid] += sred[tid + o];
        __syncthreads();
    }
    const float losssum = sred[0];
    __syncthreads();

    float r = 0.f;
    for (int i = tid; i < PC; i += 256) r += g_regpart[i];
    sred[tid] = r; __syncthreads();
    for (int o = 128; o; o >>= 1) {
        if (tid < o) sred[tid] += sred[tid + o];
        __syncthreads();
    }
    if (tid == 0) {
        const float reg = sred[0] / ((float)PC * (float)(PK * (PK - 1)));
        out[0] = losssum / (float)PB + TAU * reg;
    }
}

// ---------------------------------------------------------------------------
extern "C" void kernel_launch(void* const* d_in, const int* in_sizes, int n_in,
                              void* d_out, int out_size)
{
    (void)in_sizes; (void)n_in; (void)out_size;
    const float* emb    = (const float*)d_in[0];
    const int*   labels = (const int*)d_in[1];
    const float* fc     = (const float*)d_in[2];
    float*       out    = (float*)d_out;

    k_norm_reg<<<PC, 320>>>(fc);
    k_gemm<<<dim3(PN / BN, PB / BM), 256>>>(emb);
    k_ce<<<PB, 256>>>(labels);
    k_final<<<1, 256>>>(out);
}

// round 4
// speedup vs baseline: 2.8194x; 2.8194x over previous
#include <cuda_runtime.h>
#include <cuda_bf16.h>
#include <cstdint>

// Problem constants
#define PB   256      // batch
#define PE   512      // embed dim
#define PC   8192     // classes
#define PK   10       // centers per class
#define PN   (PC*PK)  // 81920 rows of fc
#define LMD        10.0f
#define INV_GAMMA  10.0f
#define TAU        0.2f
#define MARGIN     0.01f

// Scratch (static device globals; no allocation allowed)
__device__ __nv_bfloat16 g_wbf[(size_t)PN * PE];   // normalized centers, bf16 (84MB)
__device__ __nv_bfloat16 g_ehi[(size_t)PB * PE];   // emb hi (bf16)
__device__ __nv_bfloat16 g_elo[(size_t)PB * PE];   // emb residual (bf16)
__device__ float g_h[(size_t)PB * PC];             // soft-pooled class similarity
__device__ float g_regpart[PC];                    // per-class regularizer partial
__device__ float g_rowloss[PB];                    // per-batch-row CE loss

// strict-upper-triangle pair index tables for K=10 (45 pairs)
__constant__ int c_pk[45] = {0,0,0,0,0,0,0,0,0, 1,1,1,1,1,1,1,1, 2,2,2,2,2,2,2,
                             3,3,3,3,3,3, 4,4,4,4,4, 5,5,5,5, 6,6,6, 7,7, 8};
__constant__ int c_pj[45] = {1,2,3,4,5,6,7,8,9, 2,3,4,5,6,7,8,9, 3,4,5,6,7,8,9,
                             4,5,6,7,8,9, 5,6,7,8,9, 6,7,8,9, 7,8,9, 8,9, 9};

// ---------------------------------------------------------------------------
// PTX helpers
// ---------------------------------------------------------------------------
__device__ __forceinline__ void cp16(uint32_t dst, const void* src) {
    asm volatile("cp.async.cg.shared.global [%0], [%1], 16;\n" :: "r"(dst), "l"(src));
}
__device__ __forceinline__ void cp_commit() { asm volatile("cp.async.commit_group;\n"); }
__device__ __forceinline__ void cp_wait1()  { asm volatile("cp.async.wait_group 1;\n"); }
__device__ __forceinline__ void cp_wait0()  { asm volatile("cp.async.wait_group 0;\n"); }

__device__ __forceinline__ void ldsm_x4(uint32_t& r0, uint32_t& r1, uint32_t& r2, uint32_t& r3, uint32_t addr) {
    asm volatile("ldmatrix.sync.aligned.m8n8.x4.shared.b16 {%0,%1,%2,%3}, [%4];\n"
                 : "=r"(r0), "=r"(r1), "=r"(r2), "=r"(r3) : "r"(addr));
}
__device__ __forceinline__ void ldsm_x2(uint32_t& r0, uint32_t& r1, uint32_t addr) {
    asm volatile("ldmatrix.sync.aligned.m8n8.x2.shared.b16 {%0,%1}, [%2];\n"
                 : "=r"(r0), "=r"(r1) : "r"(addr));
}
__device__ __forceinline__ void mma16816(float* c, const uint32_t* a, const uint32_t* b) {
    asm volatile("mma.sync.aligned.m16n8k16.row.col.f32.bf16.bf16.f32 "
                 "{%0,%1,%2,%3}, {%4,%5,%6,%7}, {%8,%9}, {%0,%1,%2,%3};\n"
                 : "+f"(c[0]), "+f"(c[1]), "+f"(c[2]), "+f"(c[3])
                 : "r"(a[0]), "r"(a[1]), "r"(a[2]), "r"(a[3]), "r"(b[0]), "r"(b[1]));
}

// ---------------------------------------------------------------------------
// Kernel 0: split emb into bf16 hi + bf16 residual.
// ---------------------------------------------------------------------------
__global__ void k_prep(const float* __restrict__ emb)
{
    const int i = blockIdx.x * 256 + threadIdx.x;
    const float v = emb[i];
    const __nv_bfloat16 h = __float2bfloat16(v);
    g_ehi[i] = h;
    g_elo[i] = __float2bfloat16(v - __bfloat162float(h));
}

// ---------------------------------------------------------------------------
// Kernel 1: per-class row L2-normalization (-> bf16) + gram regularizer.
// One block per class: 10 rows x 512 in smem fp32, 10 warps.
// ---------------------------------------------------------------------------
__global__ void k_norm_reg(const float* __restrict__ fc)
{
    __shared__ float sw[10][PE];
    __shared__ float wpart[10];

    const int c    = blockIdx.x;
    const int warp = threadIdx.x >> 5;
    const int lane = threadIdx.x & 31;

    if (warp < 10) {
        const float* row = fc + ((size_t)c * PK + warp) * PE;
        float ss = 0.f;
#pragma unroll
        for (int q = 0; q < 4; q++) {
            float4 t = reinterpret_cast<const float4*>(row)[lane + 32 * q];
            reinterpret_cast<float4*>(&sw[warp][0])[lane + 32 * q] = t;
            ss += t.x * t.x + t.y * t.y + t.z * t.z + t.w * t.w;
        }
#pragma unroll
        for (int o = 16; o; o >>= 1) ss += __shfl_xor_sync(0xffffffffu, ss, o);
        const float inv = 1.0f / fmaxf(sqrtf(ss), 1e-12f);
        __nv_bfloat162* gw = reinterpret_cast<__nv_bfloat162*>(g_wbf + ((size_t)c * PK + warp) * PE);
#pragma unroll
        for (int q = 0; q < 4; q++) {
            float4 t = reinterpret_cast<float4*>(&sw[warp][0])[lane + 32 * q];
            t.x *= inv; t.y *= inv; t.z *= inv; t.w *= inv;
            reinterpret_cast<float4*>(&sw[warp][0])[lane + 32 * q] = t;
            gw[2 * (lane + 32 * q) + 0] = __floats2bfloat162_rn(t.x, t.y);
            gw[2 * (lane + 32 * q) + 1] = __floats2bfloat162_rn(t.z, t.w);
        }
    }
    __syncthreads();

    float acc = 0.f;
    for (int p = warp; p < 45; p += 10) {
        const int a = c_pk[p], b = c_pj[p];
        float d = 0.f;
#pragma unroll
        for (int q = 0; q < 4; q++) {
            float4 va = reinterpret_cast<const float4*>(&sw[a][0])[lane + 32 * q];
            float4 vb = reinterpret_cast<const float4*>(&sw[b][0])[lane + 32 * q];
            d += va.x * vb.x + va.y * vb.y + va.z * vb.z + va.w * vb.w;
        }
#pragma unroll
        for (int o = 16; o; o >>= 1) d += __shfl_xor_sync(0xffffffffu, d, o);
        float s = 1.0f - d;
        s = (s <= 0.f) ? 1e-10f : s;
        acc += sqrtf(2.0f * s);
    }
    if (lane == 0) wpart[warp] = acc;
    __syncthreads();
    if (threadIdx.x == 0) {
        float t = 0.f;
#pragma unroll
        for (int i = 0; i < 10; i++) t += wpart[i];
        g_regpart[c] = t;
    }
}

// ---------------------------------------------------------------------------
// Kernel 2: tensor-core GEMM x = (e_hi + e_lo) @ w.T, fused softmax-pool.
// Block: 128(m) x 160(n) x BK=16, 8 warps as 2(m) x 4(n); warp tile 64x40
// (= 4 whole classes). cp.async double buffer; padded smem rows (24 bf16).
// ---------------------------------------------------------------------------
#define GBM 128
#define GBN 160
#define GBK 16
#define PAD_ROW 24   // 16 bf16 data + 8 pad -> 48B row stride (conflict-free LDSM)

__global__ __launch_bounds__(256, 1) void k_gemm_mma()
{
    // smem overlay: tiles during mainloop, xs[] during epilogue
    __shared__ alignas(16) char smraw[39936];
    __nv_bfloat16* sAhi = reinterpret_cast<__nv_bfloat16*>(smraw);                 // [2][128][24]
    __nv_bfloat16* sAlo = reinterpret_cast<__nv_bfloat16*>(smraw + 12288);         // [2][128][24]
    __nv_bfloat16* sB   = reinterpret_cast<__nv_bfloat16*>(smraw + 24576);         // [2][160][24]
    float*         xs   = reinterpret_cast<float*>(smraw);                         // [8][16][40]

    const int tid    = threadIdx.x;
    const int lane   = tid & 31;
    const int warp   = tid >> 5;
    const int warp_m = warp >> 2;      // 0..1
    const int warp_n = warp & 3;       // 0..3
    const int m0     = blockIdx.y * GBM;
    const int n0     = blockIdx.x * GBN;

    const uint32_t sAhi_u = (uint32_t)__cvta_generic_to_shared(sAhi);
    const uint32_t sAlo_u = (uint32_t)__cvta_generic_to_shared(sAlo);
    const uint32_t sB_u   = (uint32_t)__cvta_generic_to_shared(sB);

    float acc[4][5][4];
#pragma unroll
    for (int i = 0; i < 4; i++)
#pragma unroll
        for (int j = 0; j < 5; j++)
#pragma unroll
            for (int r = 0; r < 4; r++) acc[i][j][r] = 0.f;

    // stage a tile (k0 = t*16) into buffer buf
    auto issue_tile = [&](int t, int buf) {
        const int k0 = t * GBK;
        {   // A_hi / A_lo: 256 chunks each, 1 per thread
            const int row = tid >> 1, half = tid & 1;
            const size_t gofs = (size_t)(m0 + row) * PE + k0 + half * 8;
            const uint32_t sofs = (uint32_t)(buf * 3072 + row * PAD_ROW + half * 8) * 2;
            cp16(sAhi_u + sofs, g_ehi + gofs);
            cp16(sAlo_u + sofs, g_elo + gofs);
        }
        {   // B: 320 chunks
            const int c0 = tid;
            const int row = c0 >> 1, half = c0 & 1;
            cp16(sB_u + (uint32_t)(buf * 3840 + row * PAD_ROW + half * 8) * 2,
                 g_wbf + (size_t)(n0 + row) * PE + k0 + half * 8);
            if (tid < 64) {
                const int c1 = tid + 256;
                const int row1 = c1 >> 1, half1 = c1 & 1;
                cp16(sB_u + (uint32_t)(buf * 3840 + row1 * PAD_ROW + half1 * 8) * 2,
                     g_wbf + (size_t)(n0 + row1) * PE + k0 + half1 * 8);
            }
        }
        cp_commit();
    };

    issue_tile(0, 0);

    const int NT = PE / GBK;   // 32
    for (int t = 0; t < NT; t++) {
        const int buf = t & 1;
        if (t + 1 < NT) { issue_tile(t + 1, buf ^ 1); cp_wait1(); }
        else            { cp_wait0(); }
        __syncthreads();

        // load B fragments (5 n-tiles), A fragments hi/lo (4 m-tiles)
        uint32_t bf[5][2];
        {
            const int r = lane & 7, sel = (lane >> 3) & 1;
#pragma unroll
            for (int jn = 0; jn < 5; jn++) {
                const int row = warp_n * 40 + jn * 8 + r;
                ldsm_x2(bf[jn][0], bf[jn][1],
                        sB_u + (uint32_t)(buf * 3840 + row * PAD_ROW + sel * 8) * 2);
            }
        }
        uint32_t ah[4][4], al[4][4];
        {
            const int r = lane & 15, sel = (lane >> 4);
#pragma unroll
            for (int mi = 0; mi < 4; mi++) {
                const int row = warp_m * 64 + mi * 16 + r;
                const uint32_t ofs = (uint32_t)(buf * 3072 + row * PAD_ROW + sel * 8) * 2;
                ldsm_x4(ah[mi][0], ah[mi][1], ah[mi][2], ah[mi][3], sAhi_u + ofs);
                ldsm_x4(al[mi][0], al[mi][1], al[mi][2], al[mi][3], sAlo_u + ofs);
            }
        }
#pragma unroll
        for (int mi = 0; mi < 4; mi++)
#pragma unroll
            for (int jn = 0; jn < 5; jn++) {
                mma16816(acc[mi][jn], ah[mi], bf[jn]);
                mma16816(acc[mi][jn], al[mi], bf[jn]);
            }
        __syncthreads();
    }

    // ---- epilogue: per m16 tile, transpose through smem, softpool K=10 ----
    float* xw = xs + warp * 640;   // [16][40] per warp
    const int cr = lane >> 2, cc = 2 * (lane & 3);
#pragma unroll
    for (int mi = 0; mi < 4; mi++) {
#pragma unroll
        for (int jn = 0; jn < 5; jn++) {
            xw[(cr + 0) * 40 + jn * 8 + cc + 0] = acc[mi][jn][0];
            xw[(cr + 0) * 40 + jn * 8 + cc + 1] = acc[mi][jn][1];
            xw[(cr + 8) * 40 + jn * 8 + cc + 0] = acc[mi][jn][2];
            xw[(cr + 8) * 40 + jn * 8 + cc + 1] = acc[mi][jn][3];
        }
        __syncwarp();
#pragma unroll
        for (int it = 0; it < 2; it++) {
            const int item = it * 32 + lane;
            const int row = item & 15, cls = item >> 4;   // cls 0..3
            const float* xp = xw + row * 40 + cls * 10;
            float mx = xp[0];
#pragma unroll
            for (int j = 1; j < 10; j++) mx = fmaxf(mx, xp[j]);
            float s = 0.f, hs = 0.f;
#pragma unroll
            for (int j = 0; j < 10; j++) {
                const float x = xp[j];
                const float e = __expf(INV_GAMMA * (x - mx));
                s += e; hs += e * x;
            }
            const int grow = m0 + warp_m * 64 + mi * 16 + row;
            const int gcls = blockIdx.x * 16 + warp_n * 4 + cls;
            g_h[(size_t)grow * PC + gcls] = hs / s;
        }
        __syncwarp();
    }
}

// ---------------------------------------------------------------------------
// Kernel 3: per-batch-row cross entropy with margin at label (labels int32).
// ---------------------------------------------------------------------------
__global__ void k_ce(const int* __restrict__ labels)
{
    __shared__ float sred[256];
    const int b   = blockIdx.x;
    const int tid = threadIdx.x;
    const float* row = g_h + (size_t)b * PC;
    const int lab = labels[b];

    float mx = -3.0e38f;
    for (int i = tid; i < PC; i += 256) {
        float v = LMD * row[i] - ((i == lab) ? (LMD * MARGIN) : 0.f);
        mx = fmaxf(mx, v);
    }
    sred[tid] = mx; __syncthreads();
    for (int o = 128; o; o >>= 1) {
        if (tid < o) sred[tid] = fmaxf(sred[tid], sred[tid + o]);
        __syncthreads();
    }
    mx = sred[0];
    __syncthreads();

    float s = 0.f;
    for (int i = tid; i < PC; i += 256) {
        float v = LMD * row[i] - ((i == lab) ? (LMD * MARGIN) : 0.f);
        s += __expf(v - mx);
    }
    sred[tid] = s; __syncthreads();
    for (int o = 128; o; o >>= 1) {
        if (tid < o) sred[tid] += sred[tid + o];
        __syncthreads();
    }
    if (tid == 0) {
        const float v = LMD * row[lab] - LMD * MARGIN;
        g_rowloss[b] = -(v - mx - logf(sred[0]));
    }
}

// ---------------------------------------------------------------------------
// Kernel 4: deterministic final reduce: mean CE + TAU * reg
// ---------------------------------------------------------------------------
__global__ void k_final(float* __restrict__ out)
{
    __shared__ float sred[256];
    const int tid = threadIdx.x;

    sred[tid] = g_rowloss[tid];
    __syncthreads();
    for (int o = 128; o; o >>= 1) {
        if (tid < o) sred[tid] += sred[tid + o];
        __syncthreads();
    }
    const float losssum = sred[0];
    __syncthreads();

    float r = 0.f;
    for (int i = tid; i < PC; i += 256) r += g_regpart[i];
    sred[tid] = r; __syncthreads();
    for (int o = 128; o; o >>= 1) {
        if (tid < o) sred[tid] += sred[tid + o];
        __syncthreads();
    }
    if (tid == 0) {
        const float reg = sred[0] / ((float)PC * (float)(PK * (PK - 1)));
        out[0] = losssum / (float)PB + TAU * reg;
    }
}

// ---------------------------------------------------------------------------
extern "C" void kernel_launch(void* const* d_in, const int* in_sizes, int n_in,
                              void* d_out, int out_size)
{
    (void)in_sizes; (void)n_in; (void)out_size;
    const float* emb    = (const float*)d_in[0];
    const int*   labels = (const int*)d_in[1];
    const float* fc     = (const float*)d_in[2];
    float*       out    = (float*)d_out;

    k_prep<<<(PB * PE) / 256, 256>>>(emb);
    k_norm_reg<<<PC, 320>>>(fc);
    k_gemm_mma<<<dim3(PN / GBN, PB / GBM), 256>>>();
    k_ce<<<PB, 256>>>(labels);
    k_final<<<1, 256>>>(out);
}

// round 5
// speedup vs baseline: 4.0804x; 1.4473x over previous
#include <cuda_runtime.h>
#include <cuda_bf16.h>
#include <cstdint>

// Problem constants
#define PB   256      // batch
#define PE   512      // embed dim
#define PC   8192     // classes
#define PK   10       // centers per class
#define PN   (PC*PK)  // 81920 rows of fc
#define LMD        10.0f
#define INV_GAMMA  10.0f
#define TAU        0.2f
#define MARGIN     0.01f

// Scratch (static device globals; no allocation allowed)
__device__ __nv_bfloat16 g_wbf[(size_t)PN * PE];   // normalized centers, bf16 (84MB)
__device__ __nv_bfloat16 g_ebf[(size_t)PB * PE];   // emb bf16
__device__ float g_h[(size_t)PB * PC];             // soft-pooled class similarity
__device__ float g_regpart[PC];                    // per-class regularizer partial
__device__ float g_rowloss[PB];                    // per-batch-row CE loss

// strict-upper-triangle pair index tables for K=10 (45 pairs)
__constant__ int c_pk[45] = {0,0,0,0,0,0,0,0,0, 1,1,1,1,1,1,1,1, 2,2,2,2,2,2,2,
                             3,3,3,3,3,3, 4,4,4,4,4, 5,5,5,5, 6,6,6, 7,7, 8};
__constant__ int c_pj[45] = {1,2,3,4,5,6,7,8,9, 2,3,4,5,6,7,8,9, 3,4,5,6,7,8,9,
                             4,5,6,7,8,9, 5,6,7,8,9, 6,7,8,9, 7,8,9, 8,9, 9};

// ---------------------------------------------------------------------------
// PTX helpers
// ---------------------------------------------------------------------------
__device__ __forceinline__ void cp16(uint32_t dst, const void* src) {
    asm volatile("cp.async.cg.shared.global [%0], [%1], 16;\n" :: "r"(dst), "l"(src));
}
__device__ __forceinline__ void cp_commit() { asm volatile("cp.async.commit_group;\n"); }
__device__ __forceinline__ void cp_wait1()  { asm volatile("cp.async.wait_group 1;\n"); }
__device__ __forceinline__ void cp_wait0()  { asm volatile("cp.async.wait_group 0;\n"); }

__device__ __forceinline__ void ldsm_x4(uint32_t& r0, uint32_t& r1, uint32_t& r2, uint32_t& r3, uint32_t addr) {
    asm volatile("ldmatrix.sync.aligned.m8n8.x4.shared.b16 {%0,%1,%2,%3}, [%4];\n"
                 : "=r"(r0), "=r"(r1), "=r"(r2), "=r"(r3) : "r"(addr));
}
__device__ __forceinline__ void ldsm_x2(uint32_t& r0, uint32_t& r1, uint32_t addr) {
    asm volatile("ldmatrix.sync.aligned.m8n8.x2.shared.b16 {%0,%1}, [%2];\n"
                 : "=r"(r0), "=r"(r1) : "r"(addr));
}
__device__ __forceinline__ void mma16816(float* c, const uint32_t* a, const uint32_t* b) {
    asm volatile("mma.sync.aligned.m16n8k16.row.col.f32.bf16.bf16.f32 "
                 "{%0,%1,%2,%3}, {%4,%5,%6,%7}, {%8,%9}, {%0,%1,%2,%3};\n"
                 : "+f"(c[0]), "+f"(c[1]), "+f"(c[2]), "+f"(c[3])
                 : "r"(a[0]), "r"(a[1]), "r"(a[2]), "r"(a[3]), "r"(b[0]), "r"(b[1]));
}

// ---------------------------------------------------------------------------
// Kernel 0: emb -> bf16
// ---------------------------------------------------------------------------
__global__ void k_prep(const float* __restrict__ emb)
{
    const int i = blockIdx.x * 256 + threadIdx.x;
    g_ebf[i] = __float2bfloat16(emb[i]);
}

// ---------------------------------------------------------------------------
// Kernel 1: per-class row L2-normalization (-> bf16) + gram regularizer.
// ---------------------------------------------------------------------------
__global__ void k_norm_reg(const float* __restrict__ fc)
{
    __shared__ float sw[10][PE];
    __shared__ float wpart[10];

    const int c    = blockIdx.x;
    const int warp = threadIdx.x >> 5;
    const int lane = threadIdx.x & 31;

    if (warp < 10) {
        const float* row = fc + ((size_t)c * PK + warp) * PE;
        float ss = 0.f;
#pragma unroll
        for (int q = 0; q < 4; q++) {
            float4 t = reinterpret_cast<const float4*>(row)[lane + 32 * q];
            reinterpret_cast<float4*>(&sw[warp][0])[lane + 32 * q] = t;
            ss += t.x * t.x + t.y * t.y + t.z * t.z + t.w * t.w;
        }
#pragma unroll
        for (int o = 16; o; o >>= 1) ss += __shfl_xor_sync(0xffffffffu, ss, o);
        const float inv = 1.0f / fmaxf(sqrtf(ss), 1e-12f);
        __nv_bfloat162* gw = reinterpret_cast<__nv_bfloat162*>(g_wbf + ((size_t)c * PK + warp) * PE);
#pragma unroll
        for (int q = 0; q < 4; q++) {
            float4 t = reinterpret_cast<float4*>(&sw[warp][0])[lane + 32 * q];
            t.x *= inv; t.y *= inv; t.z *= inv; t.w *= inv;
            reinterpret_cast<float4*>(&sw[warp][0])[lane + 32 * q] = t;
            gw[2 * (lane + 32 * q) + 0] = __floats2bfloat162_rn(t.x, t.y);
            gw[2 * (lane + 32 * q) + 1] = __floats2bfloat162_rn(t.z, t.w);
        }
    }
    __syncthreads();

    float acc = 0.f;
    for (int p = warp; p < 45; p += 10) {
        const int a = c_pk[p], b = c_pj[p];
        float d = 0.f;
#pragma unroll
        for (int q = 0; q < 4; q++) {
            float4 va = reinterpret_cast<const float4*>(&sw[a][0])[lane + 32 * q];
            float4 vb = reinterpret_cast<const float4*>(&sw[b][0])[lane + 32 * q];
            d += va.x * vb.x + va.y * vb.y + va.z * vb.z + va.w * vb.w;
        }
#pragma unroll
        for (int o = 16; o; o >>= 1) d += __shfl_xor_sync(0xffffffffu, d, o);
        float s = 1.0f - d;
        s = (s <= 0.f) ? 1e-10f : s;
        acc += sqrtf(2.0f * s);
    }
    if (lane == 0) wpart[warp] = acc;
    __syncthreads();
    if (threadIdx.x == 0) {
        float t = 0.f;
#pragma unroll
        for (int i = 0; i < 10; i++) t += wpart[i];
        g_regpart[c] = t;
    }
}

// ---------------------------------------------------------------------------
// Kernel 2: tensor-core GEMM x = e_bf @ w.T, fused softmax-pool.
// Block 128(m) x 160(n) x BK=32; 8 warps as 2(m) x 4(n); warp tile 64x40
// (= 4 whole classes). cp.async double buffer; padded rows (40 bf16 = 80B).
// ---------------------------------------------------------------------------
#define GBM 128
#define GBN 160
#define GBK 32
#define PAD_ROW 40   // 32 data + 8 pad -> 80B stride, conflict-free LDSM
#define A_STAGE (GBM * PAD_ROW)      // 5120 elems
#define B_STAGE (GBN * PAD_ROW)      // 6400 elems

__global__ __launch_bounds__(256, 1) void k_gemm_mma()
{
    // smem overlay: tiles during mainloop, xs[] during epilogue
    __shared__ alignas(16) char smraw[(A_STAGE + B_STAGE) * 2 * 2];  // 46080B
    __nv_bfloat16* sA = reinterpret_cast<__nv_bfloat16*>(smraw);                     // [2][128][40]
    __nv_bfloat16* sB = reinterpret_cast<__nv_bfloat16*>(smraw + A_STAGE * 4);       // [2][160][40]
    float*         xs = reinterpret_cast<float*>(smraw);                             // [8][16][40]

    const int tid    = threadIdx.x;
    const int lane   = tid & 31;
    const int warp   = tid >> 5;
    const int warp_m = warp >> 2;      // 0..1
    const int warp_n = warp & 3;       // 0..3
    const int m0     = blockIdx.y * GBM;
    const int n0     = blockIdx.x * GBN;

    const uint32_t sA_u = (uint32_t)__cvta_generic_to_shared(sA);
    const uint32_t sB_u = (uint32_t)__cvta_generic_to_shared(sB);

    float acc[4][5][4];
#pragma unroll
    for (int i = 0; i < 4; i++)
#pragma unroll
        for (int j = 0; j < 5; j++)
#pragma unroll
            for (int r = 0; r < 4; r++) acc[i][j][r] = 0.f;

    // stage K-slab k0 = t*32 into buffer buf
    auto issue_tile = [&](int t, int buf) {
        const int k0 = t * GBK;
        // A: 128 rows x 4 chunks(16B) = 512
#pragma unroll
        for (int idx = tid; idx < 512; idx += 256) {
            const int row = idx >> 2, quad = idx & 3;
            cp16(sA_u + (uint32_t)(buf * A_STAGE + row * PAD_ROW + quad * 8) * 2,
                 g_ebf + (size_t)(m0 + row) * PE + k0 + quad * 8);
        }
        // B: 160 rows x 4 chunks = 640
#pragma unroll
        for (int idx = tid; idx < 640; idx += 256) {
            const int row = idx >> 2, quad = idx & 3;
            cp16(sB_u + (uint32_t)(buf * B_STAGE + row * PAD_ROW + quad * 8) * 2,
                 g_wbf + (size_t)(n0 + row) * PE + k0 + quad * 8);
        }
        cp_commit();
    };

    issue_tile(0, 0);

    const int NT = PE / GBK;   // 16
    for (int t = 0; t < NT; t++) {
        const int buf = t & 1;
        if (t + 1 < NT) { issue_tile(t + 1, buf ^ 1); cp_wait1(); }
        else            { cp_wait0(); }
        __syncthreads();

#pragma unroll
        for (int ks = 0; ks < 2; ks++) {   // two k16 steps per stage
            uint32_t bf[5][2];
            {
                const int r = lane & 7, sel = (lane >> 3) & 1;
#pragma unroll
                for (int jn = 0; jn < 5; jn++) {
                    const int row = warp_n * 40 + jn * 8 + r;
                    ldsm_x2(bf[jn][0], bf[jn][1],
                            sB_u + (uint32_t)(buf * B_STAGE + row * PAD_ROW + ks * 16 + sel * 8) * 2);
                }
            }
            uint32_t af[4][4];
            {
                const int r = lane & 15, sel = lane >> 4;
#pragma unroll
                for (int mi = 0; mi < 4; mi++) {
                    const int row = warp_m * 64 + mi * 16 + r;
                    ldsm_x4(af[mi][0], af[mi][1], af[mi][2], af[mi][3],
                            sA_u + (uint32_t)(buf * A_STAGE + row * PAD_ROW + ks * 16 + sel * 8) * 2);
                }
            }
#pragma unroll
            for (int mi = 0; mi < 4; mi++)
#pragma unroll
                for (int jn = 0; jn < 5; jn++)
                    mma16816(acc[mi][jn], af[mi], bf[jn]);
        }
        __syncthreads();
    }

    // ---- epilogue: per m16 tile, transpose through smem, softpool K=10 ----
    float* xw = xs + warp * 640;   // [16][40] per warp
    const int cr = lane >> 2, cc = 2 * (lane & 3);
#pragma unroll
    for (int mi = 0; mi < 4; mi++) {
#pragma unroll
        for (int jn = 0; jn < 5; jn++) {
            xw[(cr + 0) * 40 + jn * 8 + cc + 0] = acc[mi][jn][0];
            xw[(cr + 0) * 40 + jn * 8 + cc + 1] = acc[mi][jn][1];
            xw[(cr + 8) * 40 + jn * 8 + cc + 0] = acc[mi][jn][2];
            xw[(cr + 8) * 40 + jn * 8 + cc + 1] = acc[mi][jn][3];
        }
        __syncwarp();
#pragma unroll
        for (int it = 0; it < 2; it++) {
            const int item = it * 32 + lane;
            const int row = item & 15, cls = item >> 4;   // cls 0..3
            const float* xp = xw + row * 40 + cls * 10;
            float mx = xp[0];
#pragma unroll
            for (int j = 1; j < 10; j++) mx = fmaxf(mx, xp[j]);
            float s = 0.f, hs = 0.f;
#pragma unroll
            for (int j = 0; j < 10; j++) {
                const float x = xp[j];
                const float e = __expf(INV_GAMMA * (x - mx));
                s += e; hs += e * x;
            }
            const int grow = m0 + warp_m * 64 + mi * 16 + row;
            const int gcls = blockIdx.x * 16 + warp_n * 4 + cls;
            g_h[(size_t)grow * PC + gcls] = hs / s;
        }
        __syncwarp();
    }
}

// ---------------------------------------------------------------------------
// Kernel 3: per-batch-row cross entropy with margin at label (labels int32).
// ---------------------------------------------------------------------------
__global__ void k_ce(const int* __restrict__ labels)
{
    __shared__ float sred[256];
    const int b   = blockIdx.x;
    const int tid = threadIdx.x;
    const float* row = g_h + (size_t)b * PC;
    const int lab = labels[b];

    float mx = -3.0e38f;
    for (int i = tid; i < PC; i += 256) {
        float v = LMD * row[i] - ((i == lab) ? (LMD * MARGIN) : 0.f);
        mx = fmaxf(mx, v);
    }
    sred[tid] = mx; __syncthreads();
    for (int o = 128; o; o >>= 1) {
        if (tid < o) sred[tid] = fmaxf(sred[tid], sred[tid + o]);
        __syncthreads();
    }
    mx = sred[0];
    __syncthreads();

    float s = 0.f;
    for (int i = tid; i < PC; i += 256) {
        float v = LMD * row[i] - ((i == lab) ? (LMD * MARGIN) : 0.f);
        s += __expf(v - mx);
    }
    sred[tid] = s; __syncthreads();
    for (int o = 128; o; o >>= 1) {
        if (tid < o) sred[tid] += sred[tid + o];
        __syncthreads();
    }
    if (tid == 0) {
        const float v = LMD * row[lab] - LMD * MARGIN;
        g_rowloss[b] = -(v - mx - logf(sred[0]));
    }
}

// ---------------------------------------------------------------------------
// Kernel 4: deterministic final reduce: mean CE + TAU * reg
// ---------------------------------------------------------------------------
__global__ void k_final(float* __restrict__ out)
{
    __shared__ float sred[256];
    const int tid = threadIdx.x;

    sred[tid] = g_rowloss[tid];
    __syncthreads();
    for (int o = 128; o; o >>= 1) {
        if (tid < o) sred[tid] += sred[tid + o];
        __syncthreads();
    }
    const float losssum = sred[0];
    __syncthreads();

    float r = 0.f;
    for (int i = tid; i < PC; i += 256) r += g_regpart[i];
    sred[tid] = r; __syncthreads();
    for (int o = 128; o; o >>= 1) {
        if (tid < o) sred[tid] += sred[tid + o];
        __syncthreads();
    }
    if (tid == 0) {
        const float reg = sred[0] / ((float)PC * (float)(PK * (PK - 1)));
        out[0] = losssum / (float)PB + TAU * reg;
    }
}

// ---------------------------------------------------------------------------
extern "C" void kernel_launch(void* const* d_in, const int* in_sizes, int n_in,
                              void* d_out, int out_size)
{
    (void)in_sizes; (void)n_in; (void)out_size;
    const float* emb    = (const float*)d_in[0];
    const int*   labels = (const int*)d_in[1];
    const float* fc     = (const float*)d_in[2];
    float*       out    = (float*)d_out;

    k_prep<<<(PB * PE) / 256, 256>>>(emb);
    k_norm_reg<<<PC, 320>>>(fc);
    k_gemm_mma<<<dim3(PN / GBN, PB / GBM), 256>>>();
    k_ce<<<PB, 256>>>(labels);
    k_final<<<1, 256>>>(out);
}

// round 7
// speedup vs baseline: 4.8652x; 1.1923x over previous
#include <cuda_runtime.h>
#include <cuda.h>
#include <cuda_bf16.h>
#include <cstdint>

// Problem constants
#define PB   256      // batch
#define PE   512      // embed dim
#define PC   8192     // classes
#define PK   10       // centers per class
#define PN   (PC*PK)  // 81920 rows of fc
#define LMD        10.0f
#define INV_GAMMA  10.0f
#define TAU        0.2f
#define MARGIN     0.01f

// Scratch (static device globals; no allocation allowed)
__device__ __nv_bfloat16 g_wbf[(size_t)PN * PE];   // normalized centers, bf16 (84MB)
__device__ __nv_bfloat16 g_ebf[(size_t)PB * PE];   // emb bf16
__device__ float g_h[(size_t)PB * PC];             // soft-pooled class similarity
__device__ float g_regpart[PC];                    // per-class regularizer partial
__device__ float g_rowloss[PB];                    // per-batch-row CE loss

// strict-upper-triangle pair index tables for K=10 (45 pairs)
__constant__ int c_pk[45] = {0,0,0,0,0,0,0,0,0, 1,1,1,1,1,1,1,1, 2,2,2,2,2,2,2,
                             3,3,3,3,3,3, 4,4,4,4,4, 5,5,5,5, 6,6,6, 7,7, 8};
__constant__ int c_pj[45] = {1,2,3,4,5,6,7,8,9, 2,3,4,5,6,7,8,9, 3,4,5,6,7,8,9,
                             4,5,6,7,8,9, 5,6,7,8,9, 6,7,8,9, 7,8,9, 8,9, 9};

// ---------------------------------------------------------------------------
// PTX helpers (TMA / mbarrier / ldmatrix / mma.sync — all base sm_90+ PTX)
// ---------------------------------------------------------------------------
__device__ __forceinline__ uint32_t smem_u32(const void* p) {
    return (uint32_t)__cvta_generic_to_shared(p);
}
#define MBAR_INIT(a, n) \
    asm volatile("mbarrier.init.shared.b64 [%0], %1;" :: "r"(a), "r"(n) : "memory")
#define MBAR_EXPECT_TX(a, b) \
    asm volatile("mbarrier.arrive.expect_tx.shared.b64 _, [%0], %1;" :: "r"(a), "r"(b) : "memory")
__device__ __forceinline__ void mbar_wait(uint32_t mbar, uint32_t parity) {
    uint32_t done = 0;
    while (!done) {
        asm volatile(
            "{\n\t.reg .pred p;\n\t"
            "mbarrier.try_wait.parity.acquire.cta.shared::cta.b64 p, [%1], %2, 0x989680;\n\t"
            "selp.b32 %0, 1, 0, p;\n\t}"
            : "=r"(done) : "r"(mbar), "r"(parity) : "memory");
    }
}
#define TMA_LOAD_2D(smem, map, cx, cy, mbar) \
    asm volatile("cp.async.bulk.tensor.2d.shared::cta.global.tile.mbarrier::complete_tx::bytes " \
                 "[%0], [%1, {%2, %3}], [%4];" \
                 :: "r"(smem), "l"(map), "r"(cx), "r"(cy), "r"(mbar) : "memory")
#define FENCE_PROXY_ASYNC() asm volatile("fence.proxy.async.shared::cta;" ::: "memory")

__device__ __forceinline__ void ldsm_x4(uint32_t& r0, uint32_t& r1, uint32_t& r2, uint32_t& r3, uint32_t addr) {
    asm volatile("ldmatrix.sync.aligned.m8n8.x4.shared.b16 {%0,%1,%2,%3}, [%4];\n"
                 : "=r"(r0), "=r"(r1), "=r"(r2), "=r"(r3) : "r"(addr));
}
__device__ __forceinline__ void ldsm_x2(uint32_t& r0, uint32_t& r1, uint32_t addr) {
    asm volatile("ldmatrix.sync.aligned.m8n8.x2.shared.b16 {%0,%1}, [%2];\n"
                 : "=r"(r0), "=r"(r1) : "r"(addr));
}
__device__ __forceinline__ void mma16816(float* c, const uint32_t* a, const uint32_t* b) {
    asm volatile("mma.sync.aligned.m16n8k16.row.col.f32.bf16.bf16.f32 "
                 "{%0,%1,%2,%3}, {%4,%5,%6,%7}, {%8,%9}, {%0,%1,%2,%3};\n"
                 : "+f"(c[0]), "+f"(c[1]), "+f"(c[2]), "+f"(c[3])
                 : "r"(a[0]), "r"(a[1]), "r"(a[2]), "r"(a[3]), "r"(b[0]), "r"(b[1]));
}

// ---------------------------------------------------------------------------
// Kernel 0: emb -> bf16
// ---------------------------------------------------------------------------
__global__ void k_prep(const float* __restrict__ emb)
{
    const int i = blockIdx.x * 256 + threadIdx.x;
    g_ebf[i] = __float2bfloat16(emb[i]);
}

// ---------------------------------------------------------------------------
// Kernel 1: per-class row L2-normalization (-> bf16) + gram regularizer.
// ---------------------------------------------------------------------------
__global__ void k_norm_reg(const float* __restrict__ fc)
{
    __shared__ float sw[10][PE];
    __shared__ float wpart[10];

    const int c    = blockIdx.x;
    const int warp = threadIdx.x >> 5;
    const int lane = threadIdx.x & 31;

    if (warp < 10) {
        const float* row = fc + ((size_t)c * PK + warp) * PE;
        float ss = 0.f;
#pragma unroll
        for (int q = 0; q < 4; q++) {
            float4 t = reinterpret_cast<const float4*>(row)[lane + 32 * q];
            reinterpret_cast<float4*>(&sw[warp][0])[lane + 32 * q] = t;
            ss += t.x * t.x + t.y * t.y + t.z * t.z + t.w * t.w;
        }
#pragma unroll
        for (int o = 16; o; o >>= 1) ss += __shfl_xor_sync(0xffffffffu, ss, o);
        const float inv = 1.0f / fmaxf(sqrtf(ss), 1e-12f);
        __nv_bfloat162* gw = reinterpret_cast<__nv_bfloat162*>(g_wbf + ((size_t)c * PK + warp) * PE);
#pragma unroll
        for (int q = 0; q < 4; q++) {
            float4 t = reinterpret_cast<float4*>(&sw[warp][0])[lane + 32 * q];
            t.x *= inv; t.y *= inv; t.z *= inv; t.w *= inv;
            reinterpret_cast<float4*>(&sw[warp][0])[lane + 32 * q] = t;
            gw[2 * (lane + 32 * q) + 0] = __floats2bfloat162_rn(t.x, t.y);
            gw[2 * (lane + 32 * q) + 1] = __floats2bfloat162_rn(t.z, t.w);
        }
    }
    __syncthreads();

    float acc = 0.f;
    for (int p = warp; p < 45; p += 10) {
        const int a = c_pk[p], b = c_pj[p];
        float d = 0.f;
#pragma unroll
        for (int q = 0; q < 4; q++) {
            float4 va = reinterpret_cast<const float4*>(&sw[a][0])[lane + 32 * q];
            float4 vb = reinterpret_cast<const float4*>(&sw[b][0])[lane + 32 * q];
            d += va.x * vb.x + va.y * vb.y + va.z * vb.z + va.w * vb.w;
        }
#pragma unroll
        for (int o = 16; o; o >>= 1) d += __shfl_xor_sync(0xffffffffu, d, o);
        float s = 1.0f - d;
        s = (s <= 0.f) ? 1e-10f : s;
        acc += sqrtf(2.0f * s);
    }
    if (lane == 0) wpart[warp] = acc;
    __syncthreads();
    if (threadIdx.x == 0) {
        float t = 0.f;
#pragma unroll
        for (int i = 0; i < 10; i++) t += wpart[i];
        g_regpart[c] = t;
    }
}

// ---------------------------------------------------------------------------
// Kernel 2: GEMM x = e @ w.T via mma.sync, TMA-staged (SW128), fused softpool.
// Block 128(m) x 160(n); KSTAGE=64, 8 stages, double buffer.
// 8 warps as 2(m) x 4(n); warp tile 64x40 (= 4 whole classes per warp col).
// ---------------------------------------------------------------------------
#define KSTAGE 64                       // 128B rows
#define NSTAGE (PE / KSTAGE)            // 8
#define A_BYTES (128 * 128)             // 16384
#define B_BYTES (160 * 128)             // 20480
#define STG_BYTES (A_BYTES + B_BYTES)   // 36864
#define GSMEM (2 * STG_BYTES + 1024)

__global__ __launch_bounds__(256, 1) void k_gemm_mma(
    const __grid_constant__ CUtensorMap tma_a,
    const __grid_constant__ CUtensorMap tma_b)
{
    extern __shared__ char dsm_raw[];
    char* dsm = (char*)(((uintptr_t)dsm_raw + 1023) & ~(uintptr_t)1023);
    const uint32_t dsm_u = smem_u32(dsm);

    __shared__ uint64_t s_mbar[2];   // full[0], full[1]

    const int tid    = threadIdx.x;
    const int lane   = tid & 31;
    const int warp   = tid >> 5;
    const int warp_m = warp >> 2;      // 0..1
    const int warp_n = warp & 3;       // 0..3
    const int m0     = blockIdx.y * 128;
    const int n0     = blockIdx.x * 160;

    const uint32_t mb0 = smem_u32(&s_mbar[0]);

    if (tid == 0) {
        MBAR_INIT(mb0 + 0, 1);
        MBAR_INIT(mb0 + 8, 1);
    }
    __syncthreads();
    if (tid == 0) {
        FENCE_PROXY_ASYNC();
#pragma unroll
        for (int s = 0; s < 2; s++) {
            MBAR_EXPECT_TX(mb0 + 8 * s, STG_BYTES);
            TMA_LOAD_2D(dsm_u + s * STG_BYTES,           &tma_a, s * KSTAGE, m0, mb0 + 8 * s);
            TMA_LOAD_2D(dsm_u + s * STG_BYTES + A_BYTES, &tma_b, s * KSTAGE, n0, mb0 + 8 * s);
        }
    }

    float acc[4][5][4];
#pragma unroll
    for (int i = 0; i < 4; i++)
#pragma unroll
        for (int j = 0; j < 5; j++)
#pragma unroll
            for (int r = 0; r < 4; r++) acc[i][j][r] = 0.f;

    // precompute per-lane rows (swizzle: 16B-chunk ci -> ci ^ (row & 7))
    const int a_r  = lane & 15, a_sel = lane >> 4;          // ldsm_x4 A
    const int b_r  = lane & 7,  b_sel = (lane >> 3) & 1;    // ldsm_x2 B

    int ph[2] = {0, 0};
    for (int t = 0; t < NSTAGE; t++) {
        const int s = t & 1;
        mbar_wait(mb0 + 8 * s, ph[s]); ph[s] ^= 1;
        const uint32_t aBase = dsm_u + s * STG_BYTES;
        const uint32_t bBase = aBase + A_BYTES;

#pragma unroll
        for (int ks = 0; ks < 4; ks++) {   // four k16 steps per stage
            uint32_t bf[5][2];
#pragma unroll
            for (int jn = 0; jn < 5; jn++) {
                const int row = warp_n * 40 + jn * 8 + b_r;
                const int ci  = ks * 2 + b_sel;
                ldsm_x2(bf[jn][0], bf[jn][1],
                        bBase + row * 128 + ((ci ^ (row & 7)) << 4));
            }
            uint32_t af[4][4];
#pragma unroll
            for (int mi = 0; mi < 4; mi++) {
                const int row = warp_m * 64 + mi * 16 + a_r;
                const int ci  = ks * 2 + a_sel;
                ldsm_x4(af[mi][0], af[mi][1], af[mi][2], af[mi][3],
                        aBase + row * 128 + ((ci ^ (row & 7)) << 4));
            }
#pragma unroll
            for (int mi = 0; mi < 4; mi++)
#pragma unroll
                for (int jn = 0; jn < 5; jn++)
                    mma16816(acc[mi][jn], af[mi], bf[jn]);
        }
        __syncthreads();
        if (tid == 0 && t + 2 < NSTAGE) {
            MBAR_EXPECT_TX(mb0 + 8 * s, STG_BYTES);
            TMA_LOAD_2D(dsm_u + s * STG_BYTES,           &tma_a, (t + 2) * KSTAGE, m0, mb0 + 8 * s);
            TMA_LOAD_2D(dsm_u + s * STG_BYTES + A_BYTES, &tma_b, (t + 2) * KSTAGE, n0, mb0 + 8 * s);
        }
    }

    // ---- epilogue: per m16 tile, transpose through smem, softpool K=10 ----
    float* xs = reinterpret_cast<float*>(dsm);
    float* xw = xs + warp * 640;   // [16][40] per warp
    const int cr = lane >> 2, cc = 2 * (lane & 3);
#pragma unroll
    for (int mi = 0; mi < 4; mi++) {
#pragma unroll
        for (int jn = 0; jn < 5; jn++) {
            xw[(cr + 0) * 40 + jn * 8 + cc + 0] = acc[mi][jn][0];
            xw[(cr + 0) * 40 + jn * 8 + cc + 1] = acc[mi][jn][1];
            xw[(cr + 8) * 40 + jn * 8 + cc + 0] = acc[mi][jn][2];
            xw[(cr + 8) * 40 + jn * 8 + cc + 1] = acc[mi][jn][3];
        }
        __syncwarp();
#pragma unroll
        for (int it = 0; it < 2; it++) {
            const int item = it * 32 + lane;
            const int row = item & 15, cls = item >> 4;   // cls 0..3
            const float* xp = xw + row * 40 + cls * 10;
            float mx = xp[0];
#pragma unroll
            for (int j = 1; j < 10; j++) mx = fmaxf(mx, xp[j]);
            float s = 0.f, hs = 0.f;
#pragma unroll
            for (int j = 0; j < 10; j++) {
                const float x = xp[j];
                const float e = __expf(INV_GAMMA * (x - mx));
                s += e; hs += e * x;
            }
            const int grow = m0 + warp_m * 64 + mi * 16 + row;
            const int gcls = blockIdx.x * 16 + warp_n * 4 + cls;
            g_h[(size_t)grow * PC + gcls] = hs / s;
        }
        __syncwarp();
    }
}

// ---------------------------------------------------------------------------
// Kernel 3: per-batch-row cross entropy with margin at label (labels int32).
// ---------------------------------------------------------------------------
__global__ void k_ce(const int* __restrict__ labels)
{
    __shared__ float sred[256];
    const int b   = blockIdx.x;
    const int tid = threadIdx.x;
    const float* row = g_h + (size_t)b * PC;
    const int lab = labels[b];

    float mx = -3.0e38f;
    for (int i = tid; i < PC; i += 256) {
        float v = LMD * row[i] - ((i == lab) ? (LMD * MARGIN) : 0.f);
        mx = fmaxf(mx, v);
    }
    sred[tid] = mx; __syncthreads();
    for (int o = 128; o; o >>= 1) {
        if (tid < o) sred[tid] = fmaxf(sred[tid], sred[tid + o]);
        __syncthreads();
    }
    mx = sred[0];
    __syncthreads();

    float s = 0.f;
    for (int i = tid; i < PC; i += 256) {
        float v = LMD * row[i] - ((i == lab) ? (LMD * MARGIN) : 0.f);
        s += __expf(v - mx);
    }
    sred[tid] = s; __syncthreads();
    for (int o = 128; o; o >>= 1) {
        if (tid < o) sred[tid] += sred[tid + o];
        __syncthreads();
    }
    if (tid == 0) {
        const float v = LMD * row[lab] - LMD * MARGIN;
        g_rowloss[b] = -(v - mx - logf(sred[0]));
    }
}

// ---------------------------------------------------------------------------
// Kernel 4: deterministic final reduce: mean CE + TAU * reg
// ---------------------------------------------------------------------------
__global__ void k_final(float* __restrict__ out)
{
    __shared__ float sred[256];
    const int tid = threadIdx.x;

    sred[tid] = g_rowloss[tid];
    __syncthreads();
    for (int o = 128; o; o >>= 1) {
        if (tid < o) sred[tid] += sred[tid + o];
        __syncthreads();
    }
    const float losssum = sred[0];
    __syncthreads();

    float r = 0.f;
    for (int i = tid; i < PC; i += 256) r += g_regpart[i];
    sred[tid] = r; __syncthreads();
    for (int o = 128; o; o >>= 1) {
        if (tid < o) sred[tid] += sred[tid + o];
        __syncthreads();
    }
    if (tid == 0) {
        const float reg = sred[0] / ((float)PC * (float)(PK * (PK - 1)));
        out[0] = losssum / (float)PB + TAU * reg;
    }
}

// ---------------------------------------------------------------------------
typedef CUresult (*EncodeFn)(CUtensorMap*, CUtensorMapDataType, cuuint32_t, void*,
                             const cuuint64_t*, const cuuint64_t*, const cuuint32_t*,
                             const cuuint32_t*, CUtensorMapInterleave, CUtensorMapSwizzle,
                             CUtensorMapL2promotion, CUtensorMapFloatOOBfill);

extern "C" void kernel_launch(void* const* d_in, const int* in_sizes, int n_in,
                              void* d_out, int out_size)
{
    (void)in_sizes; (void)n_in; (void)out_size;
    const float* emb    = (const float*)d_in[0];
    const int*   labels = (const int*)d_in[1];
    const float* fc     = (const float*)d_in[2];
    float*       out    = (float*)d_out;

    // Build TMA descriptors (host-side driver call via runtime entry point; no alloc)
    void* encode_raw = nullptr;
    cudaDriverEntryPointQueryResult qr;
    cudaGetDriverEntryPoint("cuTensorMapEncodeTiled", &encode_raw, cudaEnableDefault, &qr);
    EncodeFn encode = (EncodeFn)encode_raw;

    void *ebf_dev = nullptr, *wbf_dev = nullptr;
    cudaGetSymbolAddress(&ebf_dev, g_ebf);
    cudaGetSymbolAddress(&wbf_dev, g_wbf);

    CUtensorMap tma_a{}, tma_b{};
    {
        cuuint64_t dims[2]    = {PE, PB};
        cuuint64_t strides[1] = {PE * 2};
        cuuint32_t box[2]     = {KSTAGE, 128};
        cuuint32_t estr[2]    = {1, 1};
        encode(&tma_a, CU_TENSOR_MAP_DATA_TYPE_BFLOAT16, 2, ebf_dev,
               dims, strides, box, estr, CU_TENSOR_MAP_INTERLEAVE_NONE,
               CU_TENSOR_MAP_SWIZZLE_128B, CU_TENSOR_MAP_L2_PROMOTION_L2_128B,
               CU_TENSOR_MAP_FLOAT_OOB_FILL_NONE);
    }
    {
        cuuint64_t dims[2]    = {PE, PN};
        cuuint64_t strides[1] = {PE * 2};
        cuuint32_t box[2]     = {KSTAGE, 160};
        cuuint32_t estr[2]    = {1, 1};
        encode(&tma_b, CU_TENSOR_MAP_DATA_TYPE_BFLOAT16, 2, wbf_dev,
               dims, strides, box, estr, CU_TENSOR_MAP_INTERLEAVE_NONE,
               CU_TENSOR_MAP_SWIZZLE_128B, CU_TENSOR_MAP_L2_PROMOTION_L2_128B,
               CU_TENSOR_MAP_FLOAT_OOB_FILL_NONE);
    }

    cudaFuncSetAttribute(k_gemm_mma, cudaFuncAttributeMaxDynamicSharedMemorySize, GSMEM);

    k_prep<<<(PB * PE) / 256, 256>>>(emb);
    k_norm_reg<<<PC, 320>>>(fc);
    k_gemm_mma<<<dim3(PN / 160, PB / 128), 256, GSMEM>>>(tma_a, tma_b);
    k_ce<<<PB, 256>>>(labels);
    k_final<<<1, 256>>>(out);
}

// round 8
// speedup vs baseline: 5.0717x; 1.0424x over previous
#include <cuda_runtime.h>
#include <cuda.h>
#include <cuda_bf16.h>
#include <cstdint>

// Problem constants
#define PB   256      // batch
#define PE   512      // embed dim
#define PC   8192     // classes
#define PK   10       // centers per class
#define PN   (PC*PK)  // 81920 rows of fc
#define LMD        10.0f
#define INV_GAMMA  10.0f
#define TAU        0.2f
#define MARGIN     0.01f

// Scratch (static device globals; no allocation allowed)
__device__ __nv_bfloat16 g_wbf[(size_t)PN * PE];   // normalized centers, bf16 (84MB)
__device__ __nv_bfloat16 g_ebf[(size_t)PB * PE];   // emb bf16
__device__ float g_h[(size_t)PB * PC];             // soft-pooled class similarity
__device__ float g_regpart[PC];                    // per-class regularizer partial
__device__ float g_rowloss[PB];                    // per-batch-row CE loss

// strict-upper-triangle pair index tables for K=10 (45 pairs)
__constant__ int c_pk[45] = {0,0,0,0,0,0,0,0,0, 1,1,1,1,1,1,1,1, 2,2,2,2,2,2,2,
                             3,3,3,3,3,3, 4,4,4,4,4, 5,5,5,5, 6,6,6, 7,7, 8};
__constant__ int c_pj[45] = {1,2,3,4,5,6,7,8,9, 2,3,4,5,6,7,8,9, 3,4,5,6,7,8,9,
                             4,5,6,7,8,9, 5,6,7,8,9, 6,7,8,9, 7,8,9, 8,9, 9};

// ---------------------------------------------------------------------------
// PTX helpers (TMA / mbarrier / ldmatrix / mma.sync — all base sm_90+ PTX)
// ---------------------------------------------------------------------------
__device__ __forceinline__ uint32_t smem_u32(const void* p) {
    return (uint32_t)__cvta_generic_to_shared(p);
}
#define MBAR_INIT(a, n) \
    asm volatile("mbarrier.init.shared.b64 [%0], %1;" :: "r"(a), "r"(n) : "memory")
#define MBAR_EXPECT_TX(a, b) \
    asm volatile("mbarrier.arrive.expect_tx.shared.b64 _, [%0], %1;" :: "r"(a), "r"(b) : "memory")
__device__ __forceinline__ void mbar_wait(uint32_t mbar, uint32_t parity) {
    uint32_t done = 0;
    while (!done) {
        asm volatile(
            "{\n\t.reg .pred p;\n\t"
            "mbarrier.try_wait.parity.acquire.cta.shared::cta.b64 p, [%1], %2, 0x989680;\n\t"
            "selp.b32 %0, 1, 0, p;\n\t}"
            : "=r"(done) : "r"(mbar), "r"(parity) : "memory");
    }
}
#define TMA_LOAD_2D(smem, map, cx, cy, mbar) \
    asm volatile("cp.async.bulk.tensor.2d.shared::cta.global.tile.mbarrier::complete_tx::bytes " \
                 "[%0], [%1, {%2, %3}], [%4];" \
                 :: "r"(smem), "l"(map), "r"(cx), "r"(cy), "r"(mbar) : "memory")
#define FENCE_PROXY_ASYNC() asm volatile("fence.proxy.async.shared::cta;" ::: "memory")

__device__ __forceinline__ void ldsm_x4(uint32_t& r0, uint32_t& r1, uint32_t& r2, uint32_t& r3, uint32_t addr) {
    asm volatile("ldmatrix.sync.aligned.m8n8.x4.shared.b16 {%0,%1,%2,%3}, [%4];\n"
                 : "=r"(r0), "=r"(r1), "=r"(r2), "=r"(r3) : "r"(addr));
}
__device__ __forceinline__ void ldsm_x2(uint32_t& r0, uint32_t& r1, uint32_t addr) {
    asm volatile("ldmatrix.sync.aligned.m8n8.x2.shared.b16 {%0,%1}, [%2];\n"
                 : "=r"(r0), "=r"(r1) : "r"(addr));
}
__device__ __forceinline__ void mma16816(float* c, const uint32_t* a, const uint32_t* b) {
    asm volatile("mma.sync.aligned.m16n8k16.row.col.f32.bf16.bf16.f32 "
                 "{%0,%1,%2,%3}, {%4,%5,%6,%7}, {%8,%9}, {%0,%1,%2,%3};\n"
                 : "+f"(c[0]), "+f"(c[1]), "+f"(c[2]), "+f"(c[3])
                 : "r"(a[0]), "r"(a[1]), "r"(a[2]), "r"(a[3]), "r"(b[0]), "r"(b[1]));
}

// ---------------------------------------------------------------------------
// Kernel 0: emb -> bf16
// ---------------------------------------------------------------------------
__global__ void k_prep(const float* __restrict__ emb)
{
    const int i = blockIdx.x * 256 + threadIdx.x;
    g_ebf[i] = __float2bfloat16(emb[i]);
}

// ---------------------------------------------------------------------------
// Kernel 1: per-class row L2-normalization (-> bf16) + gram regularizer.
// ---------------------------------------------------------------------------
__global__ void k_norm_reg(const float* __restrict__ fc)
{
    __shared__ float sw[10][PE];
    __shared__ float wpart[10];

    const int c    = blockIdx.x;
    const int warp = threadIdx.x >> 5;
    const int lane = threadIdx.x & 31;

    if (warp < 10) {
        const float* row = fc + ((size_t)c * PK + warp) * PE;
        float ss = 0.f;
#pragma unroll
        for (int q = 0; q < 4; q++) {
            float4 t = reinterpret_cast<const float4*>(row)[lane + 32 * q];
            reinterpret_cast<float4*>(&sw[warp][0])[lane + 32 * q] = t;
            ss += t.x * t.x + t.y * t.y + t.z * t.z + t.w * t.w;
        }
#pragma unroll
        for (int o = 16; o; o >>= 1) ss += __shfl_xor_sync(0xffffffffu, ss, o);
        const float inv = 1.0f / fmaxf(sqrtf(ss), 1e-12f);
        __nv_bfloat162* gw = reinterpret_cast<__nv_bfloat162*>(g_wbf + ((size_t)c * PK + warp) * PE);
#pragma unroll
        for (int q = 0; q < 4; q++) {
            float4 t = reinterpret_cast<float4*>(&sw[warp][0])[lane + 32 * q];
            t.x *= inv; t.y *= inv; t.z *= inv; t.w *= inv;
            reinterpret_cast<float4*>(&sw[warp][0])[lane + 32 * q] = t;
            gw[2 * (lane + 32 * q) + 0] = __floats2bfloat162_rn(t.x, t.y);
            gw[2 * (lane + 32 * q) + 1] = __floats2bfloat162_rn(t.z, t.w);
        }
    }
    __syncthreads();

    float acc = 0.f;
    for (int p = warp; p < 45; p += 10) {
        const int a = c_pk[p], b = c_pj[p];
        float d = 0.f;
#pragma unroll
        for (int q = 0; q < 4; q++) {
            float4 va = reinterpret_cast<const float4*>(&sw[a][0])[lane + 32 * q];
            float4 vb = reinterpret_cast<const float4*>(&sw[b][0])[lane + 32 * q];
            d += va.x * vb.x + va.y * vb.y + va.z * vb.z + va.w * vb.w;
        }
#pragma unroll
        for (int o = 16; o; o >>= 1) d += __shfl_xor_sync(0xffffffffu, d, o);
        float s = 1.0f - d;
        s = (s <= 0.f) ? 1e-10f : s;
        acc += sqrtf(2.0f * s);
    }
    if (lane == 0) wpart[warp] = acc;
    __syncthreads();
    if (threadIdx.x == 0) {
        float t = 0.f;
#pragma unroll
        for (int i = 0; i < 10; i++) t += wpart[i];
        g_regpart[c] = t;
    }
}

// ---------------------------------------------------------------------------
// Kernel 2: GEMM x = e @ w.T via mma.sync, TMA-staged (SW128), fused softpool.
// Block 128(m) x 80(n); KSTAGE=64, 8 stages, double buffer; occupancy 2.
// 8 warps as 4(m) x 2(n); warp tile 32x40 (= 4 whole classes per warp).
// Fragment double-buffering hides ldsm latency under mma.
// ---------------------------------------------------------------------------
#define KSTAGE 64                       // 128B rows
#define NSTAGE (PE / KSTAGE)            // 8
#define NBLK  80
#define A_BYTES (128 * 128)             // 16384
#define B_BYTES (NBLK * 128)            // 10240
#define STG_BYTES (A_BYTES + B_BYTES)   // 26624
#define GSMEM (2 * STG_BYTES + 1024)    // 54272

__global__ __launch_bounds__(256, 2) void k_gemm_mma(
    const __grid_constant__ CUtensorMap tma_a,
    const __grid_constant__ CUtensorMap tma_b)
{
    extern __shared__ char dsm_raw[];
    char* dsm = (char*)(((uintptr_t)dsm_raw + 1023) & ~(uintptr_t)1023);
    const uint32_t dsm_u = smem_u32(dsm);

    __shared__ uint64_t s_mbar[2];   // full[0], full[1]

    const int tid    = threadIdx.x;
    const int lane   = tid & 31;
    const int warp   = tid >> 5;
    const int warp_m = warp >> 1;      // 0..3
    const int warp_n = warp & 1;       // 0..1
    const int m0     = blockIdx.y * 128;
    const int n0     = blockIdx.x * NBLK;

    const uint32_t mb0 = smem_u32(&s_mbar[0]);

    if (tid == 0) {
        MBAR_INIT(mb0 + 0, 1);
        MBAR_INIT(mb0 + 8, 1);
    }
    __syncthreads();
    if (tid == 0) {
        FENCE_PROXY_ASYNC();
#pragma unroll
        for (int s = 0; s < 2; s++) {
            MBAR_EXPECT_TX(mb0 + 8 * s, STG_BYTES);
            TMA_LOAD_2D(dsm_u + s * STG_BYTES,           &tma_a, s * KSTAGE, m0, mb0 + 8 * s);
            TMA_LOAD_2D(dsm_u + s * STG_BYTES + A_BYTES, &tma_b, s * KSTAGE, n0, mb0 + 8 * s);
        }
    }

    float acc[2][5][4];
#pragma unroll
    for (int i = 0; i < 2; i++)
#pragma unroll
        for (int j = 0; j < 5; j++)
#pragma unroll
            for (int r = 0; r < 4; r++) acc[i][j][r] = 0.f;

    // per-lane fragment rows (TMA SW128 swizzle: 16B-chunk ci -> ci ^ (row & 7))
    const int a_r  = lane & 15, a_sel = lane >> 4;          // ldsm_x4 A
    const int b_r  = lane & 7,  b_sel = (lane >> 3) & 1;    // ldsm_x2 B

    uint32_t af[2][2][4];   // [buf][mi][frag]
    uint32_t bfr[2][5][2];  // [buf][jn][frag]

    int ph[2] = {0, 0};
    for (int t = 0; t < NSTAGE; t++) {
        const int s = t & 1;
        mbar_wait(mb0 + 8 * s, ph[s]); ph[s] ^= 1;
        const uint32_t aBase = dsm_u + s * STG_BYTES;
        const uint32_t bBase = aBase + A_BYTES;

        // prime fragments for ks=0
        {
#pragma unroll
            for (int jn = 0; jn < 5; jn++) {
                const int row = warp_n * 40 + jn * 8 + b_r;
                ldsm_x2(bfr[0][jn][0], bfr[0][jn][1],
                        bBase + row * 128 + ((b_sel ^ (row & 7)) << 4));
            }
#pragma unroll
            for (int mi = 0; mi < 2; mi++) {
                const int row = warp_m * 32 + mi * 16 + a_r;
                ldsm_x4(af[0][mi][0], af[0][mi][1], af[0][mi][2], af[0][mi][3],
                        aBase + row * 128 + ((a_sel ^ (row & 7)) << 4));
            }
        }
#pragma unroll
        for (int ks = 0; ks < 4; ks++) {
            const int cur = ks & 1, nxt = cur ^ 1;
            if (ks < 3) {   // prefetch ks+1 fragments while mma on ks
#pragma unroll
                for (int jn = 0; jn < 5; jn++) {
                    const int row = warp_n * 40 + jn * 8 + b_r;
                    const int ci  = (ks + 1) * 2 + b_sel;
                    ldsm_x2(bfr[nxt][jn][0], bfr[nxt][jn][1],
                            bBase + row * 128 + ((ci ^ (row & 7)) << 4));
                }
#pragma unroll
                for (int mi = 0; mi < 2; mi++) {
                    const int row = warp_m * 32 + mi * 16 + a_r;
                    const int ci  = (ks + 1) * 2 + a_sel;
                    ldsm_x4(af[nxt][mi][0], af[nxt][mi][1], af[nxt][mi][2], af[nxt][mi][3],
                            aBase + row * 128 + ((ci ^ (row & 7)) << 4));
                }
            }
#pragma unroll
            for (int mi = 0; mi < 2; mi++)
#pragma unroll
                for (int jn = 0; jn < 5; jn++)
                    mma16816(acc[mi][jn], af[cur][mi], bfr[cur][jn]);
        }
        __syncthreads();
        if (tid == 0 && t + 2 < NSTAGE) {
            MBAR_EXPECT_TX(mb0 + 8 * s, STG_BYTES);
            TMA_LOAD_2D(dsm_u + s * STG_BYTES,           &tma_a, (t + 2) * KSTAGE, m0, mb0 + 8 * s);
            TMA_LOAD_2D(dsm_u + s * STG_BYTES + A_BYTES, &tma_b, (t + 2) * KSTAGE, n0, mb0 + 8 * s);
        }
    }

    // ---- epilogue: per m16 tile, transpose through smem, softpool K=10 ----
    float* xs = reinterpret_cast<float*>(dsm);
    float* xw = xs + warp * 640;   // [16][40] per warp
    const int cr = lane >> 2, cc = 2 * (lane & 3);
#pragma unroll
    for (int mi = 0; mi < 2; mi++) {
#pragma unroll
        for (int jn = 0; jn < 5; jn++) {
            xw[(cr + 0) * 40 + jn * 8 + cc + 0] = acc[mi][jn][0];
            xw[(cr + 0) * 40 + jn * 8 + cc + 1] = acc[mi][jn][1];
            xw[(cr + 8) * 40 + jn * 8 + cc + 0] = acc[mi][jn][2];
            xw[(cr + 8) * 40 + jn * 8 + cc + 1] = acc[mi][jn][3];
        }
        __syncwarp();
#pragma unroll
        for (int it = 0; it < 2; it++) {
            const int item = it * 32 + lane;
            const int row = item & 15, cls = item >> 4;   // cls 0..3
            const float* xp = xw + row * 40 + cls * 10;
            float mx = xp[0];
#pragma unroll
            for (int j = 1; j < 10; j++) mx = fmaxf(mx, xp[j]);
            float s = 0.f, hs = 0.f;
#pragma unroll
            for (int j = 0; j < 10; j++) {
                const float x = xp[j];
                const float e = __expf(INV_GAMMA * (x - mx));
                s += e; hs += e * x;
            }
            const int grow = m0 + warp_m * 32 + mi * 16 + row;
            const int gcls = blockIdx.x * 8 + warp_n * 4 + cls;
            g_h[(size_t)grow * PC + gcls] = hs / s;
        }
        __syncwarp();
    }
}

// ---------------------------------------------------------------------------
// Kernel 3: per-batch-row cross entropy with margin at label (labels int32).
// ---------------------------------------------------------------------------
__global__ void k_ce(const int* __restrict__ labels)
{
    __shared__ float sred[256];
    const int b   = blockIdx.x;
    const int tid = threadIdx.x;
    const float* row = g_h + (size_t)b * PC;
    const int lab = labels[b];

    float mx = -3.0e38f;
    for (int i = tid; i < PC; i += 256) {
        float v = LMD * row[i] - ((i == lab) ? (LMD * MARGIN) : 0.f);
        mx = fmaxf(mx, v);
    }
    sred[tid] = mx; __syncthreads();
    for (int o = 128; o; o >>= 1) {
        if (tid < o) sred[tid] = fmaxf(sred[tid], sred[tid + o]);
        __syncthreads();
    }
    mx = sred[0];
    __syncthreads();

    float s = 0.f;
    for (int i = tid; i < PC; i += 256) {
        float v = LMD * row[i] - ((i == lab) ? (LMD * MARGIN) : 0.f);
        s += __expf(v - mx);
    }
    sred[tid] = s; __syncthreads();
    for (int o = 128; o; o >>= 1) {
        if (tid < o) sred[tid] += sred[tid + o];
        __syncthreads();
    }
    if (tid == 0) {
        const float v = LMD * row[lab] - LMD * MARGIN;
        g_rowloss[b] = -(v - mx - logf(sred[0]));
    }
}

// ---------------------------------------------------------------------------
// Kernel 4: deterministic final reduce: mean CE + TAU * reg
// ---------------------------------------------------------------------------
__global__ void k_final(float* __restrict__ out)
{
    __shared__ float sred[256];
    const int tid = threadIdx.x;

    sred[tid] = g_rowloss[tid];
    __syncthreads();
    for (int o = 128; o; o >>= 1) {
        if (tid < o) sred[tid] += sred[tid + o];
        __syncthreads();
    }
    const float losssum = sred[0];
    __syncthreads();

    float r = 0.f;
    for (int i = tid; i < PC; i += 256) r += g_regpart[i];
    sred[tid] = r; __syncthreads();
    for (int o = 128; o; o >>= 1) {
        if (tid < o) sred[tid] += sred[tid + o];
        __syncthreads();
    }
    if (tid == 0) {
        const float reg = sred[0] / ((float)PC * (float)(PK * (PK - 1)));
        out[0] = losssum / (float)PB + TAU * reg;
    }
}

// ---------------------------------------------------------------------------
typedef CUresult (*EncodeFn)(CUtensorMap*, CUtensorMapDataType, cuuint32_t, void*,
                             const cuuint64_t*, const cuuint64_t*, const cuuint32_t*,
                             const cuuint32_t*, CUtensorMapInterleave, CUtensorMapSwizzle,
                             CUtensorMapL2promotion, CUtensorMapFloatOOBfill);

extern "C" void kernel_launch(void* const* d_in, const int* in_sizes, int n_in,
                              void* d_out, int out_size)
{
    (void)in_sizes; (void)n_in; (void)out_size;
    const float* emb    = (const float*)d_in[0];
    const int*   labels = (const int*)d_in[1];
    const float* fc     = (const float*)d_in[2];
    float*       out    = (float*)d_out;

    // Build TMA descriptors (host-side driver call via runtime entry point; no alloc)
    void* encode_raw = nullptr;
    cudaDriverEntryPointQueryResult qr;
    cudaGetDriverEntryPoint("cuTensorMapEncodeTiled", &encode_raw, cudaEnableDefault, &qr);
    EncodeFn encode = (EncodeFn)encode_raw;

    void *ebf_dev = nullptr, *wbf_dev = nullptr;
    cudaGetSymbolAddress(&ebf_dev, g_ebf);
    cudaGetSymbolAddress(&wbf_dev, g_wbf);

    CUtensorMap tma_a{}, tma_b{};
    {
        cuuint64_t dims[2]    = {PE, PB};
        cuuint64_t strides[1] = {PE * 2};
        cuuint32_t box[2]     = {KSTAGE, 128};
        cuuint32_t estr[2]    = {1, 1};
        encode(&tma_a, CU_TENSOR_MAP_DATA_TYPE_BFLOAT16, 2, ebf_dev,
               dims, strides, box, estr, CU_TENSOR_MAP_INTERLEAVE_NONE,
               CU_TENSOR_MAP_SWIZZLE_128B, CU_TENSOR_MAP_L2_PROMOTION_L2_128B,
               CU_TENSOR_MAP_FLOAT_OOB_FILL_NONE);
    }
    {
        cuuint64_t dims[2]    = {PE, PN};
        cuuint64_t strides[1] = {PE * 2};
        cuuint32_t box[2]     = {KSTAGE, NBLK};
        cuuint32_t estr[2]    = {1, 1};
        encode(&tma_b, CU_TENSOR_MAP_DATA_TYPE_BFLOAT16, 2, wbf_dev,
               dims, strides, box, estr, CU_TENSOR_MAP_INTERLEAVE_NONE,
               CU_TENSOR_MAP_SWIZZLE_128B, CU_TENSOR_MAP_L2_PROMOTION_L2_128B,
               CU_TENSOR_MAP_FLOAT_OOB_FILL_NONE);
    }

    cudaFuncSetAttribute(k_gemm_mma, cudaFuncAttributeMaxDynamicSharedMemorySize, GSMEM);

    k_prep<<<(PB * PE) / 256, 256>>>(emb);
    k_norm_reg<<<PC, 320>>>(fc);
    k_gemm_mma<<<dim3(PN / NBLK, PB / 128), 256, GSMEM>>>(tma_a, tma_b);
    k_ce<<<PB, 256>>>(labels);
    k_final<<<1, 256>>>(out);
}

// round 9
// speedup vs baseline: 5.1915x; 1.0236x over previous
#include <cuda_runtime.h>
#include <cuda.h>
#include <cuda_bf16.h>
#include <cstdint>

// Problem constants
#define PB   256      // batch
#define PE   512      // embed dim
#define PC   8192     // classes
#define PK   10       // centers per class
#define PN   (PC*PK)  // 81920 rows of fc
#define LMD        10.0f
#define INV_GAMMA  10.0f
#define TAU        0.2f
#define MARGIN     0.01f

// Scratch (static device globals; no allocation allowed)
__device__ __nv_bfloat16 g_wbf[(size_t)PN * PE];   // normalized centers, bf16 (84MB)
__device__ __nv_bfloat16 g_ebf[(size_t)PB * PE];   // emb bf16
__device__ float g_h[(size_t)PB * PC];             // soft-pooled class similarity
__device__ float g_regpart[PC];                    // per-class regularizer partial
__device__ float g_rowloss[PB];                    // per-batch-row CE loss
__device__ int   g_ctr = 0;                        // completion counter (self-resetting)

// strict-upper-triangle pair index tables for K=10 (45 pairs)
__constant__ int c_pk[45] = {0,0,0,0,0,0,0,0,0, 1,1,1,1,1,1,1,1, 2,2,2,2,2,2,2,
                             3,3,3,3,3,3, 4,4,4,4,4, 5,5,5,5, 6,6,6, 7,7, 8};
__constant__ int c_pj[45] = {1,2,3,4,5,6,7,8,9, 2,3,4,5,6,7,8,9, 3,4,5,6,7,8,9,
                             4,5,6,7,8,9, 5,6,7,8,9, 6,7,8,9, 7,8,9, 8,9, 9};

// ---------------------------------------------------------------------------
// PTX helpers (TMA / mbarrier / ldmatrix / mma.sync — all base sm_90+ PTX)
// ---------------------------------------------------------------------------
__device__ __forceinline__ uint32_t smem_u32(const void* p) {
    return (uint32_t)__cvta_generic_to_shared(p);
}
#define MBAR_INIT(a, n) \
    asm volatile("mbarrier.init.shared.b64 [%0], %1;" :: "r"(a), "r"(n) : "memory")
#define MBAR_EXPECT_TX(a, b) \
    asm volatile("mbarrier.arrive.expect_tx.shared.b64 _, [%0], %1;" :: "r"(a), "r"(b) : "memory")
__device__ __forceinline__ void mbar_wait(uint32_t mbar, uint32_t parity) {
    uint32_t done = 0;
    while (!done) {
        asm volatile(
            "{\n\t.reg .pred p;\n\t"
            "mbarrier.try_wait.parity.acquire.cta.shared::cta.b64 p, [%1], %2, 0x989680;\n\t"
            "selp.b32 %0, 1, 0, p;\n\t}"
            : "=r"(done) : "r"(mbar), "r"(parity) : "memory");
    }
}
#define TMA_LOAD_2D(smem, map, cx, cy, mbar) \
    asm volatile("cp.async.bulk.tensor.2d.shared::cta.global.tile.mbarrier::complete_tx::bytes " \
                 "[%0], [%1, {%2, %3}], [%4];" \
                 :: "r"(smem), "l"(map), "r"(cx), "r"(cy), "r"(mbar) : "memory")
#define FENCE_PROXY_ASYNC() asm volatile("fence.proxy.async.shared::cta;" ::: "memory")

__device__ __forceinline__ void ldsm_x4(uint32_t& r0, uint32_t& r1, uint32_t& r2, uint32_t& r3, uint32_t addr) {
    asm volatile("ldmatrix.sync.aligned.m8n8.x4.shared.b16 {%0,%1,%2,%3}, [%4];\n"
                 : "=r"(r0), "=r"(r1), "=r"(r2), "=r"(r3) : "r"(addr));
}
__device__ __forceinline__ void ldsm_x2(uint32_t& r0, uint32_t& r1, uint32_t addr) {
    asm volatile("ldmatrix.sync.aligned.m8n8.x2.shared.b16 {%0,%1}, [%2];\n"
                 : "=r"(r0), "=r"(r1) : "r"(addr));
}
__device__ __forceinline__ void mma16816(float* c, const uint32_t* a, const uint32_t* b) {
    asm volatile("mma.sync.aligned.m16n8k16.row.col.f32.bf16.bf16.f32 "
                 "{%0,%1,%2,%3}, {%4,%5,%6,%7}, {%8,%9}, {%0,%1,%2,%3};\n"
                 : "+f"(c[0]), "+f"(c[1]), "+f"(c[2]), "+f"(c[3])
                 : "r"(a[0]), "r"(a[1]), "r"(a[2]), "r"(a[3]), "r"(b[0]), "r"(b[1]));
}

// ---------------------------------------------------------------------------
// Kernel 0: emb -> bf16
// ---------------------------------------------------------------------------
__global__ void k_prep(const float* __restrict__ emb)
{
    const int i = blockIdx.x * 256 + threadIdx.x;
    g_ebf[i] = __float2bfloat16(emb[i]);
}

// ---------------------------------------------------------------------------
// Kernel 1: per-class row L2-normalization (-> bf16) + gram regularizer.
// ---------------------------------------------------------------------------
__global__ void k_norm_reg(const float* __restrict__ fc)
{
    __shared__ float sw[10][PE];
    __shared__ float wpart[10];

    const int c    = blockIdx.x;
    const int warp = threadIdx.x >> 5;
    const int lane = threadIdx.x & 31;

    if (warp < 10) {
        const float* row = fc + ((size_t)c * PK + warp) * PE;
        float ss = 0.f;
#pragma unroll
        for (int q = 0; q < 4; q++) {
            float4 t = reinterpret_cast<const float4*>(row)[lane + 32 * q];
            reinterpret_cast<float4*>(&sw[warp][0])[lane + 32 * q] = t;
            ss += t.x * t.x + t.y * t.y + t.z * t.z + t.w * t.w;
        }
#pragma unroll
        for (int o = 16; o; o >>= 1) ss += __shfl_xor_sync(0xffffffffu, ss, o);
        const float inv = 1.0f / fmaxf(sqrtf(ss), 1e-12f);
        __nv_bfloat162* gw = reinterpret_cast<__nv_bfloat162*>(g_wbf + ((size_t)c * PK + warp) * PE);
#pragma unroll
        for (int q = 0; q < 4; q++) {
            float4 t = reinterpret_cast<float4*>(&sw[warp][0])[lane + 32 * q];
            t.x *= inv; t.y *= inv; t.z *= inv; t.w *= inv;
            reinterpret_cast<float4*>(&sw[warp][0])[lane + 32 * q] = t;
            gw[2 * (lane + 32 * q) + 0] = __floats2bfloat162_rn(t.x, t.y);
            gw[2 * (lane + 32 * q) + 1] = __floats2bfloat162_rn(t.z, t.w);
        }
    }
    __syncthreads();

    float acc = 0.f;
    for (int p = warp; p < 45; p += 10) {
        const int a = c_pk[p], b = c_pj[p];
        float d = 0.f;
#pragma unroll
        for (int q = 0; q < 4; q++) {
            float4 va = reinterpret_cast<const float4*>(&sw[a][0])[lane + 32 * q];
            float4 vb = reinterpret_cast<const float4*>(&sw[b][0])[lane + 32 * q];
            d += va.x * vb.x + va.y * vb.y + va.z * vb.z + va.w * vb.w;
        }
#pragma unroll
        for (int o = 16; o; o >>= 1) d += __shfl_xor_sync(0xffffffffu, d, o);
        float s = 1.0f - d;
        s = (s <= 0.f) ? 1e-10f : s;
        acc += sqrtf(2.0f * s);
    }
    if (lane == 0) wpart[warp] = acc;
    __syncthreads();
    if (threadIdx.x == 0) {
        float t = 0.f;
#pragma unroll
        for (int i = 0; i < 10; i++) t += wpart[i];
        g_regpart[c] = t;
    }
}

// ---------------------------------------------------------------------------
// Kernel 2: GEMM x = e @ w.T via mma.sync, TMA-staged (SW128), fused softpool.
// Block 128(m) x 80(n); KSTAGE=64, 8 stages, 3-slot TMA ring; occupancy 2.
// 8 warps as 4(m) x 2(n); warp tile 32x40 (= 4 whole classes per warp).
// Fragment double-buffering hides ldsm latency under mma.
// ---------------------------------------------------------------------------
#define KSTAGE 64                       // 128B rows
#define NSTAGE (PE / KSTAGE)            // 8
#define NSLOT 3
#define NBLK  80
#define A_BYTES (128 * 128)             // 16384
#define B_BYTES (NBLK * 128)            // 10240
#define STG_BYTES (A_BYTES + B_BYTES)   // 26624
#define GSMEM (NSLOT * STG_BYTES + 1024)  // 80896

__global__ __launch_bounds__(256, 2) void k_gemm_mma(
    const __grid_constant__ CUtensorMap tma_a,
    const __grid_constant__ CUtensorMap tma_b)
{
    extern __shared__ char dsm_raw[];
    char* dsm = (char*)(((uintptr_t)dsm_raw + 1023) & ~(uintptr_t)1023);
    const uint32_t dsm_u = smem_u32(dsm);

    __shared__ uint64_t s_mbar[NSLOT];   // full barriers

    const int tid    = threadIdx.x;
    const int lane   = tid & 31;
    const int warp   = tid >> 5;
    const int warp_m = warp >> 1;      // 0..3
    const int warp_n = warp & 1;       // 0..1
    const int m0     = blockIdx.y * 128;
    const int n0     = blockIdx.x * NBLK;

    const uint32_t mb0 = smem_u32(&s_mbar[0]);

    if (tid == 0) {
#pragma unroll
        for (int s = 0; s < NSLOT; s++) MBAR_INIT(mb0 + 8 * s, 1);
    }
    __syncthreads();
    if (tid == 0) {
        FENCE_PROXY_ASYNC();
#pragma unroll
        for (int s = 0; s < NSLOT; s++) {
            MBAR_EXPECT_TX(mb0 + 8 * s, STG_BYTES);
            TMA_LOAD_2D(dsm_u + s * STG_BYTES,           &tma_a, s * KSTAGE, m0, mb0 + 8 * s);
            TMA_LOAD_2D(dsm_u + s * STG_BYTES + A_BYTES, &tma_b, s * KSTAGE, n0, mb0 + 8 * s);
        }
    }

    float acc[2][5][4];
#pragma unroll
    for (int i = 0; i < 2; i++)
#pragma unroll
        for (int j = 0; j < 5; j++)
#pragma unroll
            for (int r = 0; r < 4; r++) acc[i][j][r] = 0.f;

    // per-lane fragment rows (TMA SW128 swizzle: 16B-chunk ci -> ci ^ (row & 7))
    const int a_r  = lane & 15, a_sel = lane >> 4;          // ldsm_x4 A
    const int b_r  = lane & 7,  b_sel = (lane >> 3) & 1;    // ldsm_x2 B

    uint32_t af[2][2][4];   // [buf][mi][frag]
    uint32_t bfr[2][5][2];  // [buf][jn][frag]

    int ph[NSLOT] = {0, 0, 0};
    for (int t = 0; t < NSTAGE; t++) {
        const int s = t % NSLOT;
        mbar_wait(mb0 + 8 * s, ph[s]); ph[s] ^= 1;
        const uint32_t aBase = dsm_u + s * STG_BYTES;
        const uint32_t bBase = aBase + A_BYTES;

        // prime fragments for ks=0
        {
#pragma unroll
            for (int jn = 0; jn < 5; jn++) {
                const int row = warp_n * 40 + jn * 8 + b_r;
                ldsm_x2(bfr[0][jn][0], bfr[0][jn][1],
                        bBase + row * 128 + ((b_sel ^ (row & 7)) << 4));
            }
#pragma unroll
            for (int mi = 0; mi < 2; mi++) {
                const int row = warp_m * 32 + mi * 16 + a_r;
                ldsm_x4(af[0][mi][0], af[0][mi][1], af[0][mi][2], af[0][mi][3],
                        aBase + row * 128 + ((a_sel ^ (row & 7)) << 4));
            }
        }
#pragma unroll
        for (int ks = 0; ks < 4; ks++) {
            const int cur = ks & 1, nxt = cur ^ 1;
            if (ks < 3) {   // prefetch ks+1 fragments while mma on ks
#pragma unroll
                for (int jn = 0; jn < 5; jn++) {
                    const int row = warp_n * 40 + jn * 8 + b_r;
                    const int ci  = (ks + 1) * 2 + b_sel;
                    ldsm_x2(bfr[nxt][jn][0], bfr[nxt][jn][1],
                            bBase + row * 128 + ((ci ^ (row & 7)) << 4));
                }
#pragma unroll
                for (int mi = 0; mi < 2; mi++) {
                    const int row = warp_m * 32 + mi * 16 + a_r;
                    const int ci  = (ks + 1) * 2 + a_sel;
                    ldsm_x4(af[nxt][mi][0], af[nxt][mi][1], af[nxt][mi][2], af[nxt][mi][3],
                            aBase + row * 128 + ((ci ^ (row & 7)) << 4));
                }
            }
#pragma unroll
            for (int mi = 0; mi < 2; mi++)
#pragma unroll
                for (int jn = 0; jn < 5; jn++)
                    mma16816(acc[mi][jn], af[cur][mi], bfr[cur][jn]);
        }
        __syncthreads();
        if (tid == 0 && t + NSLOT < NSTAGE) {
            MBAR_EXPECT_TX(mb0 + 8 * s, STG_BYTES);
            TMA_LOAD_2D(dsm_u + s * STG_BYTES,           &tma_a, (t + NSLOT) * KSTAGE, m0, mb0 + 8 * s);
            TMA_LOAD_2D(dsm_u + s * STG_BYTES + A_BYTES, &tma_b, (t + NSLOT) * KSTAGE, n0, mb0 + 8 * s);
        }
    }

    // ---- epilogue: per m16 tile, transpose through smem, softpool K=10 ----
    float* xs = reinterpret_cast<float*>(dsm);
    float* xw = xs + warp * 640;   // [16][40] per warp
    const int cr = lane >> 2, cc = 2 * (lane & 3);
#pragma unroll
    for (int mi = 0; mi < 2; mi++) {
#pragma unroll
        for (int jn = 0; jn < 5; jn++) {
            xw[(cr + 0) * 40 + jn * 8 + cc + 0] = acc[mi][jn][0];
            xw[(cr + 0) * 40 + jn * 8 + cc + 1] = acc[mi][jn][1];
            xw[(cr + 8) * 40 + jn * 8 + cc + 0] = acc[mi][jn][2];
            xw[(cr + 8) * 40 + jn * 8 + cc + 1] = acc[mi][jn][3];
        }
        __syncwarp();
#pragma unroll
        for (int it = 0; it < 2; it++) {
            const int item = it * 32 + lane;
            const int row = item & 15, cls = item >> 4;   // cls 0..3
            const float* xp = xw + row * 40 + cls * 10;
            float mx = xp[0];
#pragma unroll
            for (int j = 1; j < 10; j++) mx = fmaxf(mx, xp[j]);
            float s = 0.f, hs = 0.f;
#pragma unroll
            for (int j = 0; j < 10; j++) {
                const float x = xp[j];
                const float e = __expf(INV_GAMMA * (x - mx));
                s += e; hs += e * x;
            }
            const int grow = m0 + warp_m * 32 + mi * 16 + row;
            const int gcls = blockIdx.x * 8 + warp_n * 4 + cls;
            g_h[(size_t)grow * PC + gcls] = hs / s;
        }
        __syncwarp();
    }
}

// ---------------------------------------------------------------------------
// Kernel 3: per-row CE (single pass, logits in registers) + fused final
// reduction performed by the last block to finish (deterministic fixed-order
// tree sums, identical math to the previous k_ce + k_final pair).
// ---------------------------------------------------------------------------
__global__ void k_ce_final(const int* __restrict__ labels, float* __restrict__ out)
{
    __shared__ float sred[256];
    __shared__ int sflag;
    const int b   = blockIdx.x;
    const int tid = threadIdx.x;
    const float* row = g_h + (size_t)b * PC;
    const int lab = labels[b];

    // one global pass: 32 strided logits per thread, kept in registers
    float v[32];
    float mx = -3.0e38f;
#pragma unroll
    for (int j = 0; j < 32; j++) {
        const int i = tid + 256 * j;
        v[j] = LMD * row[i] - ((i == lab) ? (LMD * MARGIN) : 0.f);
        mx = fmaxf(mx, v[j]);
    }
    sred[tid] = mx; __syncthreads();
    for (int o = 128; o; o >>= 1) {
        if (tid < o) sred[tid] = fmaxf(sred[tid], sred[tid + o]);
        __syncthreads();
    }
    mx = sred[0];
    __syncthreads();

    float s = 0.f;
#pragma unroll
    for (int j = 0; j < 32; j++) s += __expf(v[j] - mx);
    sred[tid] = s; __syncthreads();
    for (int o = 128; o; o >>= 1) {
        if (tid < o) sred[tid] += sred[tid + o];
        __syncthreads();
    }

    if (tid == 0) {
        const float vl = LMD * row[lab] - LMD * MARGIN;
        g_rowloss[b] = -(vl - mx - logf(sred[0]));
        __threadfence();
        const int old = atomicAdd(&g_ctr, 1);
        sflag = (old == PB - 1) ? 1 : 0;
    }
    __syncthreads();
    if (!sflag) return;

    // ---- last block: final deterministic reduction ----
    __threadfence();
    sred[tid] = g_rowloss[tid];
    __syncthreads();
    for (int o = 128; o; o >>= 1) {
        if (tid < o) sred[tid] += sred[tid + o];
        __syncthreads();
    }
    const float losssum = sred[0];
    __syncthreads();

    float r = 0.f;
    for (int i = tid; i < PC; i += 256) r += g_regpart[i];
    sred[tid] = r; __syncthreads();
    for (int o = 128; o; o >>= 1) {
        if (tid < o) sred[tid] += sred[tid + o];
        __syncthreads();
    }
    if (tid == 0) {
        const float reg = sred[0] / ((float)PC * (float)(PK * (PK - 1)));
        out[0] = losssum / (float)PB + TAU * reg;
        g_ctr = 0;   // reset for next graph replay (deterministic)
    }
}

// ---------------------------------------------------------------------------
typedef CUresult (*EncodeFn)(CUtensorMap*, CUtensorMapDataType, cuuint32_t, void*,
                             const cuuint64_t*, const cuuint64_t*, const cuuint32_t*,
                             const cuuint32_t*, CUtensorMapInterleave, CUtensorMapSwizzle,
                             CUtensorMapL2promotion, CUtensorMapFloatOOBfill);

extern "C" void kernel_launch(void* const* d_in, const int* in_sizes, int n_in,
                              void* d_out, int out_size)
{
    (void)in_sizes; (void)n_in; (void)out_size;
    const float* emb    = (const float*)d_in[0];
    const int*   labels = (const int*)d_in[1];
    const float* fc     = (const float*)d_in[2];
    float*       out    = (float*)d_out;

    // Build TMA descriptors (host-side driver call via runtime entry point; no alloc)
    void* encode_raw = nullptr;
    cudaDriverEntryPointQueryResult qr;
    cudaGetDriverEntryPoint("cuTensorMapEncodeTiled", &encode_raw, cudaEnableDefault, &qr);
    EncodeFn encode = (EncodeFn)encode_raw;

    void *ebf_dev = nullptr, *wbf_dev = nullptr;
    cudaGetSymbolAddress(&ebf_dev, g_ebf);
    cudaGetSymbolAddress(&wbf_dev, g_wbf);

    CUtensorMap tma_a{}, tma_b{};
    {
        cuuint64_t dims[2]    = {PE, PB};
        cuuint64_t strides[1] = {PE * 2};
        cuuint32_t box[2]     = {KSTAGE, 128};
        cuuint32_t estr[2]    = {1, 1};
        encode(&tma_a, CU_TENSOR_MAP_DATA_TYPE_BFLOAT16, 2, ebf_dev,
               dims, strides, box, estr, CU_TENSOR_MAP_INTERLEAVE_NONE,
               CU_TENSOR_MAP_SWIZZLE_128B, CU_TENSOR_MAP_L2_PROMOTION_L2_128B,
               CU_TENSOR_MAP_FLOAT_OOB_FILL_NONE);
    }
    {
        cuuint64_t dims[2]    = {PE, PN};
        cuuint64_t strides[1] = {PE * 2};
        cuuint32_t box[2]     = {KSTAGE, NBLK};
        cuuint32_t estr[2]    = {1, 1};
        encode(&tma_b, CU_TENSOR_MAP_DATA_TYPE_BFLOAT16, 2, wbf_dev,
               dims, strides, box, estr, CU_TENSOR_MAP_INTERLEAVE_NONE,
               CU_TENSOR_MAP_SWIZZLE_128B, CU_TENSOR_MAP_L2_PROMOTION_L2_128B,
               CU_TENSOR_MAP_FLOAT_OOB_FILL_NONE);
    }

    cudaFuncSetAttribute(k_gemm_mma, cudaFuncAttributeMaxDynamicSharedMemorySize, GSMEM);

    k_prep<<<(PB * PE) / 256, 256>>>(emb);
    k_norm_reg<<<PC, 320>>>(fc);
    k_gemm_mma<<<dim3(PN / NBLK, PB / 128), 256, GSMEM>>>(tma_a, tma_b);
    k_ce_final<<<PB, 256>>>(labels, out);
}